// round 2
// baseline (speedup 1.0000x reference)
#include <cuda_runtime.h>

#define B_ 32
#define S_ 257
#define D_ 1024
#define H_ 16
#define HD_ 64
#define E_ 8
#define R_ 16
#define KE_ 2
#define MTOT (B_*S_)
#define SCALE_Q 0.125f

// ---------------- scratch (device globals: allocation-free) ----------------
__device__ float g_q [(size_t)MTOT * D_];
__device__ float g_k [(size_t)MTOT * D_];
__device__ float g_v [(size_t)MTOT * D_];
__device__ float g_x2[(size_t)MTOT * D_];
__device__ float g_sc[(size_t)B_ * H_ * S_ * S_];
__device__ float g_xa[(size_t)B_ * KE_ * S_ * R_];

// ---------------- xa[b,k,s,r] = sum_d X[b,s,d] * A[idx[b,k],r,d] ----------
__global__ __launch_bounds__(256) void xa_kernel(
    const float* __restrict__ X, const float* __restrict__ A,
    const int* __restrict__ idx, float* __restrict__ xa)
{
    int bs = blockIdx.x;
    int b = bs / S_, s = bs - b * S_;
    __shared__ float xs[D_];
    const float* xrow = X + (size_t)bs * D_;
    for (int i = threadIdx.x; i < D_; i += 256) xs[i] = xrow[i];
    __syncthreads();
    int w = threadIdx.x >> 5, lane = threadIdx.x & 31;
    for (int p = w; p < KE_ * R_; p += 8) {
        int k = p >> 4, r = p & 15;
        int e = idx[b * KE_ + k];
        const float* ar = A + ((size_t)e * R_ + r) * D_;
        float sum = 0.f;
        for (int d = lane; d < D_; d += 32) sum = fmaf(xs[d], ar[d], sum);
        #pragma unroll
        for (int o = 16; o; o >>= 1) sum += __shfl_xor_sync(0xffffffffu, sum, o);
        if (!lane) xa[(((size_t)b * KE_ + k) * S_ + s) * R_ + r] = sum;
    }
}

// ---------------- Y = X @ W^T + bias + LoRA, times scale -------------------
// 64x64 tile, BK=16, 256 threads, 4x4 microtile per thread.
__global__ __launch_bounds__(256) void gemm_lora(
    const float* __restrict__ X, const float* __restrict__ W,
    const float* __restrict__ bias, const float* __restrict__ Bm,
    const int* __restrict__ idx, const float* __restrict__ gates,
    const float* __restrict__ xa, float* __restrict__ Y, float scale)
{
    __shared__ float Xs[16][64];
    __shared__ float Ws[16][64];
    int tm = blockIdx.y << 6, tn = blockIdx.x << 6;
    int t = threadIdx.x;
    int lrow = t >> 2, lcol = (t & 3) << 2;
    int tx = t & 15, ty = t >> 4;
    float acc[4][4] = {};
    bool xv = (tm + lrow) < MTOT;
    const float* Xp = X + (size_t)(tm + lrow) * D_ + lcol;
    const float* Wp = W + (size_t)(tn + lrow) * D_ + lcol;

    for (int k0 = 0; k0 < D_; k0 += 16) {
        float4 xq = xv ? *(const float4*)(Xp + k0) : make_float4(0.f, 0.f, 0.f, 0.f);
        float4 wq = *(const float4*)(Wp + k0);
        __syncthreads();
        Xs[lcol  ][lrow] = xq.x; Xs[lcol+1][lrow] = xq.y;
        Xs[lcol+2][lrow] = xq.z; Xs[lcol+3][lrow] = xq.w;
        Ws[lcol  ][lrow] = wq.x; Ws[lcol+1][lrow] = wq.y;
        Ws[lcol+2][lrow] = wq.z; Ws[lcol+3][lrow] = wq.w;
        __syncthreads();
        #pragma unroll
        for (int kk = 0; kk < 16; kk++) {
            float4 wr = *(const float4*)&Ws[kk][tx << 2];
            float wr4[4] = {wr.x, wr.y, wr.z, wr.w};
            float xr[4];
            #pragma unroll
            for (int i = 0; i < 4; i++) xr[i] = Xs[kk][(ty << 2) + i];
            #pragma unroll
            for (int i = 0; i < 4; i++)
                #pragma unroll
                for (int j = 0; j < 4; j++)
                    acc[i][j] = fmaf(xr[i], wr4[j], acc[i][j]);
        }
    }

    int col0 = tn + (tx << 2);
    #pragma unroll
    for (int i = 0; i < 4; i++) {
        int m = tm + (ty << 2) + i;
        if (m >= MTOT) break;
        int b = m / S_, s = m - b * S_;
        float lres[4] = {0.f, 0.f, 0.f, 0.f};
        #pragma unroll
        for (int k = 0; k < KE_; k++) {
            int e = idx[b * KE_ + k];
            float g = gates[b * KE_ + k];
            const float* xp = xa + (((size_t)b * KE_ + k) * S_ + s) * R_;
            const float* bp = Bm + ((size_t)e * D_ + col0) * R_;
            #pragma unroll
            for (int r = 0; r < R_; r++) {
                float xvg = g * xp[r];
                lres[0] = fmaf(xvg, bp[r          ], lres[0]);
                lres[1] = fmaf(xvg, bp[R_   + r   ], lres[1]);
                lres[2] = fmaf(xvg, bp[2*R_ + r   ], lres[2]);
                lres[3] = fmaf(xvg, bp[3*R_ + r   ], lres[3]);
            }
        }
        float* yp = Y + (size_t)m * D_ + col0;
        #pragma unroll
        for (int j = 0; j < 4; j++)
            yp[j] = (acc[i][j] + bias[col0 + j] + lres[j]) * scale;
    }
}

// ---------------- scores[bh,s,t] = q[bh,s,:] . k[bh,t,:] -------------------
__global__ __launch_bounds__(256) void attn_scores(
    const float* __restrict__ Q, const float* __restrict__ Kk)
{
    int bh = blockIdx.z; int b = bh >> 4, h = bh & 15;
    int tm = blockIdx.y << 6, tn = blockIdx.x << 6;
    __shared__ float Qs[16][64];
    __shared__ float Ks[16][64];
    int t = threadIdx.x;
    int lrow = t >> 2, lcol = (t & 3) << 2;
    int tx = t & 15, ty = t >> 4;
    float acc[4][4] = {};
    bool qv = (tm + lrow) < S_;
    bool kv = (tn + lrow) < S_;
    const float* Qp = Q + ((size_t)b * S_ + tm + lrow) * D_ + h * HD_ + lcol;
    const float* Kp = Kk + ((size_t)b * S_ + tn + lrow) * D_ + h * HD_ + lcol;

    for (int k0 = 0; k0 < HD_; k0 += 16) {
        float4 qq = qv ? *(const float4*)(Qp + k0) : make_float4(0.f,0.f,0.f,0.f);
        float4 kq = kv ? *(const float4*)(Kp + k0) : make_float4(0.f,0.f,0.f,0.f);
        __syncthreads();
        Qs[lcol  ][lrow] = qq.x; Qs[lcol+1][lrow] = qq.y;
        Qs[lcol+2][lrow] = qq.z; Qs[lcol+3][lrow] = qq.w;
        Ks[lcol  ][lrow] = kq.x; Ks[lcol+1][lrow] = kq.y;
        Ks[lcol+2][lrow] = kq.z; Ks[lcol+3][lrow] = kq.w;
        __syncthreads();
        #pragma unroll
        for (int kk = 0; kk < 16; kk++) {
            float4 kr = *(const float4*)&Ks[kk][tx << 2];
            float kr4[4] = {kr.x, kr.y, kr.z, kr.w};
            float qr[4];
            #pragma unroll
            for (int i = 0; i < 4; i++) qr[i] = Qs[kk][(ty << 2) + i];
            #pragma unroll
            for (int i = 0; i < 4; i++)
                #pragma unroll
                for (int j = 0; j < 4; j++)
                    acc[i][j] = fmaf(qr[i], kr4[j], acc[i][j]);
        }
    }

    float* sp = g_sc + (size_t)bh * S_ * S_;
    #pragma unroll
    for (int i = 0; i < 4; i++) {
        int s = tm + (ty << 2) + i;
        if (s >= S_) break;
        #pragma unroll
        for (int j = 0; j < 4; j++) {
            int tt = tn + (tx << 2) + j;
            if (tt < S_) sp[(size_t)s * S_ + tt] = acc[i][j];
        }
    }
}

// ---------------- row softmax over t (length 257) --------------------------
__global__ __launch_bounds__(256) void softmax_k()
{
    size_t row = blockIdx.x;
    float* p = g_sc + row * S_;
    int t = threadIdx.x;
    float v0 = p[t];
    float v1 = (t == 0) ? p[256] : -1e30f;
    __shared__ float sm[256];
    sm[t] = fmaxf(v0, v1);
    __syncthreads();
    #pragma unroll
    for (int o = 128; o; o >>= 1) {
        if (t < o) sm[t] = fmaxf(sm[t], sm[t + o]);
        __syncthreads();
    }
    float rmax = sm[0];
    __syncthreads();
    float e0 = __expf(v0 - rmax);
    float e1 = (t == 0) ? __expf(v1 - rmax) : 0.f;
    sm[t] = e0 + e1;
    __syncthreads();
    #pragma unroll
    for (int o = 128; o; o >>= 1) {
        if (t < o) sm[t] += sm[t + o];
        __syncthreads();
    }
    float inv = 1.f / sm[0];
    p[t] = e0 * inv;
    if (t == 0) p[256] = e1 * inv;
}

// ---------------- out[bh,s,d] = sum_t attn[s,t] * v[bh,t,d] ----------------
__global__ __launch_bounds__(256) void attn_av(
    const float* __restrict__ V, float* __restrict__ Xo)
{
    int bh = blockIdx.z; int b = bh >> 4, h = bh & 15;
    int tm = blockIdx.y << 6;
    __shared__ float As[16][64];
    __shared__ float Vs[16][64];
    int t = threadIdx.x;
    int arow = t >> 2, acol = (t & 3) << 2;
    int vrow = t >> 4, vcol = (t & 15) << 2;
    int tx = t & 15, ty = t >> 4;
    float acc[4][4] = {};
    const float* sp = g_sc + (size_t)bh * S_ * S_;

    for (int k0 = 0; k0 < S_; k0 += 16) {
        int srow = tm + arow;
        bool sv = srow < S_;
        const float* ap = sp + (size_t)srow * S_ + k0 + acol;
        float a0 = (sv && (k0 + acol + 0) < S_) ? ap[0] : 0.f;
        float a1 = (sv && (k0 + acol + 1) < S_) ? ap[1] : 0.f;
        float a2 = (sv && (k0 + acol + 2) < S_) ? ap[2] : 0.f;
        float a3 = (sv && (k0 + acol + 3) < S_) ? ap[3] : 0.f;
        bool vv = (k0 + vrow) < S_;
        float4 vq = vv ? *(const float4*)(V + ((size_t)b * S_ + k0 + vrow) * D_ + h * HD_ + vcol)
                       : make_float4(0.f, 0.f, 0.f, 0.f);
        __syncthreads();
        As[acol  ][arow] = a0; As[acol+1][arow] = a1;
        As[acol+2][arow] = a2; As[acol+3][arow] = a3;
        Vs[vrow][vcol  ] = vq.x; Vs[vrow][vcol+1] = vq.y;
        Vs[vrow][vcol+2] = vq.z; Vs[vrow][vcol+3] = vq.w;
        __syncthreads();
        #pragma unroll
        for (int kk = 0; kk < 16; kk++) {
            float4 vr = *(const float4*)&Vs[kk][tx << 2];
            float vr4[4] = {vr.x, vr.y, vr.z, vr.w};
            float ar[4];
            #pragma unroll
            for (int i = 0; i < 4; i++) ar[i] = As[kk][(ty << 2) + i];
            #pragma unroll
            for (int i = 0; i < 4; i++)
                #pragma unroll
                for (int j = 0; j < 4; j++)
                    acc[i][j] = fmaf(ar[i], vr4[j], acc[i][j]);
        }
    }

    #pragma unroll
    for (int i = 0; i < 4; i++) {
        int s = tm + (ty << 2) + i;
        if (s >= S_) break;
        float* op = Xo + ((size_t)b * S_ + s) * D_ + h * HD_ + (tx << 2);
        #pragma unroll
        for (int j = 0; j < 4; j++) op[j] = acc[i][j];
    }
}

// ---------------- host launcher --------------------------------------------
extern "C" void kernel_launch(void* const* d_in, const int* in_sizes, int n_in,
                              void* d_out, int out_size)
{
    const float* hs    = (const float*)d_in[0];
    const int*   idx   = (const int*)  d_in[1];
    const float* gates = (const float*)d_in[2];
    const float* wq = (const float*)d_in[3];  const float* Aq = (const float*)d_in[4];
    const float* Bq = (const float*)d_in[5];  const float* bq = (const float*)d_in[6];
    const float* wk = (const float*)d_in[7];  const float* Ak = (const float*)d_in[8];
    const float* Bk = (const float*)d_in[9];  const float* bk = (const float*)d_in[10];
    const float* wv = (const float*)d_in[11]; const float* Av = (const float*)d_in[12];
    const float* Bv = (const float*)d_in[13]; const float* bv = (const float*)d_in[14];
    const float* wo = (const float*)d_in[15]; const float* Ao = (const float*)d_in[16];
    const float* Bo = (const float*)d_in[17]; const float* bo = (const float*)d_in[18];
    float* out = (float*)d_out;

    float *q, *k, *v, *x2, *xa;
    cudaGetSymbolAddress((void**)&q,  g_q);
    cudaGetSymbolAddress((void**)&k,  g_k);
    cudaGetSymbolAddress((void**)&v,  g_v);
    cudaGetSymbolAddress((void**)&x2, g_x2);
    cudaGetSymbolAddress((void**)&xa, g_xa);

    dim3 gg(16, (MTOT + 63) / 64);  // 16 x 129

    xa_kernel<<<MTOT, 256>>>(hs, Aq, idx, xa);
    gemm_lora<<<gg, 256>>>(hs, wq, bq, Bq, idx, gates, xa, q, SCALE_Q);
    xa_kernel<<<MTOT, 256>>>(hs, Ak, idx, xa);
    gemm_lora<<<gg, 256>>>(hs, wk, bk, Bk, idx, gates, xa, k, 1.f);
    xa_kernel<<<MTOT, 256>>>(hs, Av, idx, xa);
    gemm_lora<<<gg, 256>>>(hs, wv, bv, Bv, idx, gates, xa, v, 1.f);

    attn_scores<<<dim3(5, 5, B_ * H_), 256>>>(q, k);
    softmax_k<<<B_ * H_ * S_, 256>>>();
    attn_av<<<dim3(1, 5, B_ * H_), 256>>>(v, x2);

    xa_kernel<<<MTOT, 256>>>(x2, Ao, idx, xa);
    gemm_lora<<<gg, 256>>>(x2, wo, bo, Bo, idx, gates, xa, out, 1.f);
}

// round 3
// speedup vs baseline: 1.7014x; 1.7014x over previous
#include <cuda_runtime.h>

#define B_ 32
#define S_ 257
#define D_ 1024
#define H_ 16
#define HD_ 64
#define E_ 8
#define R_ 16
#define KE_ 2
#define MTOT (B_*S_)
#define SCALE_Q 0.125f

// ---------------- scratch (device globals: allocation-free) ----------------
__device__ float g_q [(size_t)MTOT * D_];
__device__ float g_k [(size_t)MTOT * D_];
__device__ float g_v [(size_t)MTOT * D_];
__device__ float g_x2[(size_t)MTOT * D_];
__device__ float g_sc[(size_t)B_ * H_ * S_ * S_];
__device__ float g_xa[(size_t)B_ * KE_ * S_ * R_];

// ============================================================================
// xa[b,slot,s,r] = sum_d X[b,s,d] * A[idx[b,slot], r, d]
// Block = (b, slot, r-half). A half (8x1024, 32KB) staged in smem once.
// Warps process s in chunks of 4 to amortize the As LDS across 4 FMAs.
// ============================================================================
__global__ __launch_bounds__(256) void xa_kernel(
    const float* __restrict__ X, const float* __restrict__ A,
    const int* __restrict__ idx, float* __restrict__ xa)
{
    int b = blockIdx.x, slot = blockIdx.y, rh = blockIdx.z;
    int e = idx[b * KE_ + slot];
    __shared__ float As[8][D_];
    const float* Ap = A + ((size_t)e * R_ + rh * 8) * D_;
    for (int i = threadIdx.x; i < 8 * D_ / 4; i += 256)
        ((float4*)As)[i] = ((const float4*)Ap)[i];
    __syncthreads();

    int w = threadIdx.x >> 5, lane = threadIdx.x & 31;
    for (int s4 = w * 4; s4 < S_; s4 += 32) {
        float sum[8][4];
        #pragma unroll
        for (int r = 0; r < 8; r++)
            #pragma unroll
            for (int si = 0; si < 4; si++) sum[r][si] = 0.f;

        #pragma unroll 1
        for (int c = 0; c < 8; c++) {
            float4 xv[4];
            #pragma unroll
            for (int si = 0; si < 4; si++) {
                int s = s4 + si;
                xv[si] = (s < S_)
                    ? *(const float4*)(X + ((size_t)b * S_ + s) * D_ + c * 128 + lane * 4)
                    : make_float4(0.f, 0.f, 0.f, 0.f);
            }
            #pragma unroll
            for (int r = 0; r < 8; r++) {
                float4 av = *(const float4*)&As[r][c * 128 + lane * 4];
                #pragma unroll
                for (int si = 0; si < 4; si++)
                    sum[r][si] = fmaf(xv[si].x, av.x,
                                 fmaf(xv[si].y, av.y,
                                 fmaf(xv[si].z, av.z,
                                 fmaf(xv[si].w, av.w, sum[r][si]))));
            }
        }
        #pragma unroll
        for (int r = 0; r < 8; r++)
            #pragma unroll
            for (int si = 0; si < 4; si++) {
                float v = sum[r][si];
                #pragma unroll
                for (int o = 16; o; o >>= 1) v += __shfl_xor_sync(0xffffffffu, v, o);
                int s = s4 + si;
                if (lane == 0 && s < S_)
                    xa[(((size_t)b * KE_ + slot) * S_ + s) * R_ + rh * 8 + r] = v;
            }
    }
}

// ============================================================================
// Y = (X @ W^T + bias) * scale      (128x128 tile, BK=16, 8x8 microtile)
// ============================================================================
__global__ __launch_bounds__(256, 2) void sgemm_bias(
    const float* __restrict__ X, const float* __restrict__ W,
    const float* __restrict__ bias, float* __restrict__ Y, float scale)
{
    __shared__ float Xs[16][128];
    __shared__ float Ws[16][128];
    const int t = threadIdx.x;
    const int tm = blockIdx.y << 7;
    const int tn = blockIdx.x << 7;
    const int tx = t & 15, ty = t >> 4;

    const int r0  = t >> 2;            // 0..63
    const int kc0 = (t & 3) << 2;      // 0,4,8,12
    const bool v0 = (tm + r0)      < MTOT;
    const bool v1 = (tm + r0 + 64) < MTOT;
    const float* Xp0 = X + (size_t)(tm + r0) * D_ + kc0;
    const float* Xp1 = Xp0 + (size_t)64 * D_;
    const float* Wp0 = W + (size_t)(tn + r0) * D_ + kc0;
    const float* Wp1 = Wp0 + (size_t)64 * D_;

    float acc[8][8] = {};

    for (int k0 = 0; k0 < D_; k0 += 16) {
        float4 x0 = v0 ? *(const float4*)(Xp0 + k0) : make_float4(0.f,0.f,0.f,0.f);
        float4 x1 = v1 ? *(const float4*)(Xp1 + k0) : make_float4(0.f,0.f,0.f,0.f);
        float4 w0 = *(const float4*)(Wp0 + k0);
        float4 w1 = *(const float4*)(Wp1 + k0);
        __syncthreads();
        Xs[kc0  ][r0]      = x0.x; Xs[kc0+1][r0]      = x0.y;
        Xs[kc0+2][r0]      = x0.z; Xs[kc0+3][r0]      = x0.w;
        Xs[kc0  ][r0 + 64] = x1.x; Xs[kc0+1][r0 + 64] = x1.y;
        Xs[kc0+2][r0 + 64] = x1.z; Xs[kc0+3][r0 + 64] = x1.w;
        Ws[kc0  ][r0]      = w0.x; Ws[kc0+1][r0]      = w0.y;
        Ws[kc0+2][r0]      = w0.z; Ws[kc0+3][r0]      = w0.w;
        Ws[kc0  ][r0 + 64] = w1.x; Ws[kc0+1][r0 + 64] = w1.y;
        Ws[kc0+2][r0 + 64] = w1.z; Ws[kc0+3][r0 + 64] = w1.w;
        __syncthreads();

        #pragma unroll
        for (int kk = 0; kk < 16; kk++) {
            float a[8], bb[8];
            *(float4*)&a[0]  = *(const float4*)&Xs[kk][ty * 8];
            *(float4*)&a[4]  = *(const float4*)&Xs[kk][ty * 8 + 4];
            *(float4*)&bb[0] = *(const float4*)&Ws[kk][tx * 8];
            *(float4*)&bb[4] = *(const float4*)&Ws[kk][tx * 8 + 4];
            #pragma unroll
            for (int i = 0; i < 8; i++)
                #pragma unroll
                for (int j = 0; j < 8; j++)
                    acc[i][j] = fmaf(a[i], bb[j], acc[i][j]);
        }
    }

    float bs[8];
    *(float4*)&bs[0] = *(const float4*)&bias[tn + tx * 8];
    *(float4*)&bs[4] = *(const float4*)&bias[tn + tx * 8 + 4];

    #pragma unroll
    for (int i = 0; i < 8; i++) {
        int m = tm + ty * 8 + i;
        if (m < MTOT) {
            float out[8];
            #pragma unroll
            for (int j = 0; j < 8; j++) out[j] = (acc[i][j] + bs[j]) * scale;
            float* yp = Y + (size_t)m * D_ + tn + tx * 8;
            *(float4*)yp       = *(float4*)&out[0];
            *(float4*)(yp + 4) = *(float4*)&out[4];
        }
    }
}

// ============================================================================
// Y[b,s,c] += scale * sum_slot gate * (xa[b,slot,s,:] . Bm[e, c, :])
// Block = (b, 64-col tile). B tiles + gated xa chunks staged in smem.
// ============================================================================
__global__ __launch_bounds__(256) void lora_add(
    const float* __restrict__ Bm, const int* __restrict__ idx,
    const float* __restrict__ gates, const float* __restrict__ xa,
    float* __restrict__ Y, float scale)
{
    int b = blockIdx.x;
    int cn = blockIdx.y << 6;
    int t = threadIdx.x;
    __shared__ float Bs[2][64][17];
    __shared__ float xs[2][64][17];
    int e0 = idx[b * KE_], e1 = idx[b * KE_ + 1];
    float g0 = gates[b * KE_] * scale, g1 = gates[b * KE_ + 1] * scale;

    for (int i = t; i < 2048; i += 256) {
        int slot = i >> 10, rem = i & 1023, c = rem >> 4, r = rem & 15;
        Bs[slot][c][r] = Bm[((size_t)(slot ? e1 : e0) * D_ + cn + c) * R_ + r];
    }

    int c = t & 63, sq = t >> 6;
    for (int s0 = 0; s0 < S_; s0 += 64) {
        __syncthreads();
        for (int i = t; i < 2048; i += 256) {
            int slot = i >> 10, rem = i & 1023, si = rem >> 4, r = rem & 15;
            int s = s0 + si;
            float v = (s < S_) ? xa[(((size_t)b * KE_ + slot) * S_ + s) * R_ + r] : 0.f;
            xs[slot][si][r] = v * (slot ? g1 : g0);
        }
        __syncthreads();
        for (int si = sq; si < 64; si += 4) {
            int s = s0 + si;
            if (s >= S_) break;
            float sum = 0.f;
            #pragma unroll
            for (int r = 0; r < 16; r++) {
                sum = fmaf(xs[0][si][r], Bs[0][c][r], sum);
                sum = fmaf(xs[1][si][r], Bs[1][c][r], sum);
            }
            Y[((size_t)b * S_ + s) * D_ + cn + c] += sum;
        }
    }
}

// ---------------- scores[bh,s,t] = q[bh,s,:] . k[bh,t,:] -------------------
__global__ __launch_bounds__(256) void attn_scores(
    const float* __restrict__ Q, const float* __restrict__ Kk)
{
    int bh = blockIdx.z; int b = bh >> 4, h = bh & 15;
    int tm = blockIdx.y << 6, tn = blockIdx.x << 6;
    __shared__ float Qs[16][64];
    __shared__ float Ks[16][64];
    int t = threadIdx.x;
    int lrow = t >> 2, lcol = (t & 3) << 2;
    int tx = t & 15, ty = t >> 4;
    float acc[4][4] = {};
    bool qv = (tm + lrow) < S_;
    bool kv = (tn + lrow) < S_;
    const float* Qp = Q + ((size_t)b * S_ + tm + lrow) * D_ + h * HD_ + lcol;
    const float* Kp = Kk + ((size_t)b * S_ + tn + lrow) * D_ + h * HD_ + lcol;

    for (int k0 = 0; k0 < HD_; k0 += 16) {
        float4 qq = qv ? *(const float4*)(Qp + k0) : make_float4(0.f,0.f,0.f,0.f);
        float4 kq = kv ? *(const float4*)(Kp + k0) : make_float4(0.f,0.f,0.f,0.f);
        __syncthreads();
        Qs[lcol  ][lrow] = qq.x; Qs[lcol+1][lrow] = qq.y;
        Qs[lcol+2][lrow] = qq.z; Qs[lcol+3][lrow] = qq.w;
        Ks[lcol  ][lrow] = kq.x; Ks[lcol+1][lrow] = kq.y;
        Ks[lcol+2][lrow] = kq.z; Ks[lcol+3][lrow] = kq.w;
        __syncthreads();
        #pragma unroll
        for (int kk = 0; kk < 16; kk++) {
            float4 kr = *(const float4*)&Ks[kk][tx << 2];
            float kr4[4] = {kr.x, kr.y, kr.z, kr.w};
            float qr[4];
            #pragma unroll
            for (int i = 0; i < 4; i++) qr[i] = Qs[kk][(ty << 2) + i];
            #pragma unroll
            for (int i = 0; i < 4; i++)
                #pragma unroll
                for (int j = 0; j < 4; j++)
                    acc[i][j] = fmaf(qr[i], kr4[j], acc[i][j]);
        }
    }

    float* sp = g_sc + (size_t)bh * S_ * S_;
    #pragma unroll
    for (int i = 0; i < 4; i++) {
        int s = tm + (ty << 2) + i;
        if (s >= S_) break;
        #pragma unroll
        for (int j = 0; j < 4; j++) {
            int tt = tn + (tx << 2) + j;
            if (tt < S_) sp[(size_t)s * S_ + tt] = acc[i][j];
        }
    }
}

// ---------------- row softmax over t (length 257) --------------------------
__global__ __launch_bounds__(256) void softmax_k()
{
    size_t row = blockIdx.x;
    float* p = g_sc + row * S_;
    int t = threadIdx.x;
    float v0 = p[t];
    float v1 = (t == 0) ? p[256] : -1e30f;
    __shared__ float sm[256];
    sm[t] = fmaxf(v0, v1);
    __syncthreads();
    #pragma unroll
    for (int o = 128; o; o >>= 1) {
        if (t < o) sm[t] = fmaxf(sm[t], sm[t + o]);
        __syncthreads();
    }
    float rmax = sm[0];
    __syncthreads();
    float e0 = __expf(v0 - rmax);
    float e1 = (t == 0) ? __expf(v1 - rmax) : 0.f;
    sm[t] = e0 + e1;
    __syncthreads();
    #pragma unroll
    for (int o = 128; o; o >>= 1) {
        if (t < o) sm[t] += sm[t + o];
        __syncthreads();
    }
    float inv = 1.f / sm[0];
    p[t] = e0 * inv;
    if (t == 0) p[256] = e1 * inv;
}

// ---------------- out[bh,s,d] = sum_t attn[s,t] * v[bh,t,d] ----------------
__global__ __launch_bounds__(256) void attn_av(
    const float* __restrict__ V, float* __restrict__ Xo)
{
    int bh = blockIdx.z; int b = bh >> 4, h = bh & 15;
    int tm = blockIdx.y << 6;
    __shared__ float As[16][64];
    __shared__ float Vs[16][64];
    int t = threadIdx.x;
    int arow = t >> 2, acol = (t & 3) << 2;
    int vrow = t >> 4, vcol = (t & 15) << 2;
    int tx = t & 15, ty = t >> 4;
    float acc[4][4] = {};
    const float* sp = g_sc + (size_t)bh * S_ * S_;

    for (int k0 = 0; k0 < S_; k0 += 16) {
        int srow = tm + arow;
        bool sv = srow < S_;
        const float* ap = sp + (size_t)srow * S_ + k0 + acol;
        float a0 = (sv && (k0 + acol + 0) < S_) ? ap[0] : 0.f;
        float a1 = (sv && (k0 + acol + 1) < S_) ? ap[1] : 0.f;
        float a2 = (sv && (k0 + acol + 2) < S_) ? ap[2] : 0.f;
        float a3 = (sv && (k0 + acol + 3) < S_) ? ap[3] : 0.f;
        bool vv = (k0 + vrow) < S_;
        float4 vq = vv ? *(const float4*)(V + ((size_t)b * S_ + k0 + vrow) * D_ + h * HD_ + vcol)
                       : make_float4(0.f, 0.f, 0.f, 0.f);
        __syncthreads();
        As[acol  ][arow] = a0; As[acol+1][arow] = a1;
        As[acol+2][arow] = a2; As[acol+3][arow] = a3;
        Vs[vrow][vcol  ] = vq.x; Vs[vrow][vcol+1] = vq.y;
        Vs[vrow][vcol+2] = vq.z; Vs[vrow][vcol+3] = vq.w;
        __syncthreads();
        #pragma unroll
        for (int kk = 0; kk < 16; kk++) {
            float4 vr = *(const float4*)&Vs[kk][tx << 2];
            float vr4[4] = {vr.x, vr.y, vr.z, vr.w};
            float ar[4];
            #pragma unroll
            for (int i = 0; i < 4; i++) ar[i] = As[kk][(ty << 2) + i];
            #pragma unroll
            for (int i = 0; i < 4; i++)
                #pragma unroll
                for (int j = 0; j < 4; j++)
                    acc[i][j] = fmaf(ar[i], vr4[j], acc[i][j]);
        }
    }

    #pragma unroll
    for (int i = 0; i < 4; i++) {
        int s = tm + (ty << 2) + i;
        if (s >= S_) break;
        float* op = Xo + ((size_t)b * S_ + s) * D_ + h * HD_ + (tx << 2);
        #pragma unroll
        for (int j = 0; j < 4; j++) op[j] = acc[i][j];
    }
}

// ---------------- host launcher --------------------------------------------
extern "C" void kernel_launch(void* const* d_in, const int* in_sizes, int n_in,
                              void* d_out, int out_size)
{
    const float* hs    = (const float*)d_in[0];
    const int*   idx   = (const int*)  d_in[1];
    const float* gates = (const float*)d_in[2];
    const float* wq = (const float*)d_in[3];  const float* Aq = (const float*)d_in[4];
    const float* Bq = (const float*)d_in[5];  const float* bq = (const float*)d_in[6];
    const float* wk = (const float*)d_in[7];  const float* Ak = (const float*)d_in[8];
    const float* Bk = (const float*)d_in[9];  const float* bk = (const float*)d_in[10];
    const float* wv = (const float*)d_in[11]; const float* Av = (const float*)d_in[12];
    const float* Bv = (const float*)d_in[13]; const float* bv = (const float*)d_in[14];
    const float* wo = (const float*)d_in[15]; const float* Ao = (const float*)d_in[16];
    const float* Bo = (const float*)d_in[17]; const float* bo = (const float*)d_in[18];
    float* out = (float*)d_out;

    float *q, *k, *v, *x2, *xa;
    cudaGetSymbolAddress((void**)&q,  g_q);
    cudaGetSymbolAddress((void**)&k,  g_k);
    cudaGetSymbolAddress((void**)&v,  g_v);
    cudaGetSymbolAddress((void**)&x2, g_x2);
    cudaGetSymbolAddress((void**)&xa, g_xa);

    dim3 gx(B_, KE_, 2);
    dim3 gg(D_ / 128, (MTOT + 127) / 128);   // 8 x 65
    dim3 gl(B_, D_ / 64);                    // 32 x 16

    xa_kernel<<<gx, 256>>>(hs, Aq, idx, xa);
    sgemm_bias<<<gg, 256>>>(hs, wq, bq, q, SCALE_Q);
    lora_add<<<gl, 256>>>(Bq, idx, gates, xa, q, SCALE_Q);

    xa_kernel<<<gx, 256>>>(hs, Ak, idx, xa);
    sgemm_bias<<<gg, 256>>>(hs, wk, bk, k, 1.f);
    lora_add<<<gl, 256>>>(Bk, idx, gates, xa, k, 1.f);

    xa_kernel<<<gx, 256>>>(hs, Av, idx, xa);
    sgemm_bias<<<gg, 256>>>(hs, wv, bv, v, 1.f);
    lora_add<<<gl, 256>>>(Bv, idx, gates, xa, v, 1.f);

    attn_scores<<<dim3(5, 5, B_ * H_), 256>>>(q, k);
    softmax_k<<<B_ * H_ * S_, 256>>>();
    attn_av<<<dim3(1, 5, B_ * H_), 256>>>(v, x2);

    xa_kernel<<<gx, 256>>>(x2, Ao, idx, xa);
    sgemm_bias<<<gg, 256>>>(x2, wo, bo, out, 1.f);
    lora_add<<<gl, 256>>>(Bo, idx, gates, xa, out, 1.f);
}

// round 5
// speedup vs baseline: 2.6971x; 1.5853x over previous
#include <cuda_runtime.h>
#include <cuda_bf16.h>
#include <cstdint>

#define B_ 32
#define S_ 257
#define D_ 1024
#define H_ 16
#define HD_ 64
#define E_ 8
#define R_ 16
#define KE_ 2
#define MTOT (B_*S_)
#define SCALE_Q 0.125f

// ---------------- scratch (device globals: allocation-free) ----------------
__device__ float g_q [(size_t)MTOT * D_];
__device__ float g_k [(size_t)MTOT * D_];
__device__ float g_v [(size_t)MTOT * D_];
__device__ float g_x2[(size_t)MTOT * D_];
__device__ float g_sc[(size_t)B_ * H_ * S_ * S_];
__device__ float g_xa[(size_t)B_ * KE_ * S_ * R_];
__device__ __nv_bfloat16 g_xhi[(size_t)MTOT * D_];
__device__ __nv_bfloat16 g_xlo[(size_t)MTOT * D_];
__device__ __nv_bfloat16 g_whi[(size_t)D_ * D_];
__device__ __nv_bfloat16 g_wlo[(size_t)D_ * D_];

// ========================= helpers (baseline PTX only) ======================
__device__ __forceinline__ uint32_t smem_u32(const void* p) {
    uint32_t a;
    asm("{ .reg .u64 t; cvta.to.shared.u64 t, %1; cvt.u32.u64 %0, t; }"
        : "=r"(a) : "l"(p));
    return a;
}

#define LDSM4(r0, r1, r2, r3, addr) \
    asm volatile("ldmatrix.sync.aligned.m8n8.x4.shared.b16 {%0,%1,%2,%3}, [%4];" \
        : "=r"(r0), "=r"(r1), "=r"(r2), "=r"(r3) : "r"(addr))

#define MMA16816(d, a, b0, b1) \
    asm volatile("mma.sync.aligned.m16n8k16.row.col.f32.bf16.bf16.f32 " \
        "{%0,%1,%2,%3}, {%4,%5,%6,%7}, {%8,%9}, {%0,%1,%2,%3};" \
        : "+f"((d)[0]), "+f"((d)[1]), "+f"((d)[2]), "+f"((d)[3]) \
        : "r"((a)[0]), "r"((a)[1]), "r"((a)[2]), "r"((a)[3]), "r"(b0), "r"(b1))

#define CP_ASYNC16(dst, src, sz) \
    asm volatile("cp.async.cg.shared.global [%0], [%1], 16, %2;" \
        :: "r"(dst), "l"(src), "r"(sz))
#define CP_COMMIT()  asm volatile("cp.async.commit_group;" ::: "memory")
#define CP_WAIT1()   asm volatile("cp.async.wait_group 1;" ::: "memory")
#define CP_WAIT0()   asm volatile("cp.async.wait_group 0;" ::: "memory")

// ============================================================================
// split fp32 -> (bf16 hi, bf16 lo) with lo = bf16(x - hi)
// ============================================================================
__global__ __launch_bounds__(256) void split_bf16(
    const float4* __restrict__ x, uint2* __restrict__ hi, uint2* __restrict__ lo, int n4)
{
    int i = blockIdx.x * 256 + threadIdx.x;
    if (i >= n4) return;
    float4 v = x[i];
    __nv_bfloat162 h01 = __floats2bfloat162_rn(v.x, v.y);
    __nv_bfloat162 h23 = __floats2bfloat162_rn(v.z, v.w);
    float lx = v.x - __bfloat162float(h01.x);
    float ly = v.y - __bfloat162float(h01.y);
    float lz = v.z - __bfloat162float(h23.x);
    float lw = v.w - __bfloat162float(h23.y);
    __nv_bfloat162 l01 = __floats2bfloat162_rn(lx, ly);
    __nv_bfloat162 l23 = __floats2bfloat162_rn(lz, lw);
    uint2 hv, lv;
    hv.x = *(uint32_t*)&h01; hv.y = *(uint32_t*)&h23;
    lv.x = *(uint32_t*)&l01; lv.y = *(uint32_t*)&l23;
    hi[i] = hv; lo[i] = lv;
}

// ============================================================================
// HMMA GEMM: Y = (Xf32 @ Wf32^T + bias) * scale   via bf16x3 split
// 128x128x32 tile, cp.async double buffer, mma.sync m16n8k16 bf16.
// smem tile: 128 rows x 32 bf16, row pitch 80B (conflict-free ldmatrix).
// ============================================================================
#define APITCH 80
#define TILEB (128 * APITCH)
#define STAGEB (4 * TILEB)
#define GEMM_SMEM (2 * STAGEB)

__device__ __forceinline__ void stage_load(
    uint32_t sb, int buf, int c, int tm, int tn, int tid,
    const __nv_bfloat16* __restrict__ Xhi, const __nv_bfloat16* __restrict__ Xlo,
    const __nv_bfloat16* __restrict__ Whi, const __nv_bfloat16* __restrict__ Wlo)
{
    uint32_t st = sb + buf * STAGEB;
    #pragma unroll
    for (int j = 0; j < 8; ++j) {
        int g = tid + j * 256;
        int tile = g >> 9, i = g & 511, row = i >> 2, seg = i & 3;
        const __nv_bfloat16* base = (tile == 0) ? Xhi : (tile == 1) ? Xlo
                                   : (tile == 2) ? Whi : Wlo;
        int grow = ((tile < 2) ? tm : tn) + row;
        const void* src = base + (size_t)grow * D_ + c * 32 + seg * 8;
        uint32_t dst = st + tile * TILEB + row * APITCH + seg * 16;
        int sz = (tile >= 2 || grow < MTOT) ? 16 : 0;
        CP_ASYNC16(dst, src, sz);
    }
}

__global__ __launch_bounds__(256) void mma_gemm(
    const __nv_bfloat16* __restrict__ Xhi, const __nv_bfloat16* __restrict__ Xlo,
    const __nv_bfloat16* __restrict__ Whi, const __nv_bfloat16* __restrict__ Wlo,
    const float* __restrict__ bias, float* __restrict__ Y, float scale)
{
    extern __shared__ char smem[];
    const uint32_t sb = smem_u32(smem);
    const int tid = threadIdx.x;
    const int wid = tid >> 5, lane = tid & 31;
    const int tm = blockIdx.y << 7, tn = blockIdx.x << 7;
    const int wm = (wid & 1) * 64, wn = (wid >> 1) * 32;

    const int lrow = lane & 15;            // ldmatrix A row within 16
    const int lk   = lane >> 4;            // 0/1 -> k halves
    const int brow = ((lane >> 4) << 3) + (lane & 7);  // B row within 16
    const int bk   = (lane >> 3) & 1;      // B k half

    float acc[4][4][4] = {};

    stage_load(sb, 0, 0, tm, tn, tid, Xhi, Xlo, Whi, Wlo);
    CP_COMMIT();

    for (int c = 0; c < 32; ++c) {
        const int buf = c & 1;
        if (c + 1 < 32) {
            stage_load(sb, buf ^ 1, c + 1, tm, tn, tid, Xhi, Xlo, Whi, Wlo);
            CP_COMMIT();
            CP_WAIT1();
        } else {
            CP_WAIT0();
        }
        __syncthreads();

        const uint32_t Ah = sb + buf * STAGEB;
        const uint32_t Al = Ah + TILEB;
        const uint32_t Bh = Ah + 2 * TILEB;
        const uint32_t Bl = Ah + 3 * TILEB;

        #pragma unroll
        for (int kk2 = 0; kk2 < 2; ++kk2) {
            const int kkb = kk2 * 32;
            uint32_t ah[4][4], al[4][4], bh[2][4], bl[2][4];
            const uint32_t aoff = (uint32_t)(wm + lrow) * APITCH + kkb + lk * 16;
            const uint32_t boff = (uint32_t)(wn + brow) * APITCH + kkb + bk * 16;
            #pragma unroll
            for (int mt = 0; mt < 4; ++mt) {
                LDSM4(ah[mt][0], ah[mt][1], ah[mt][2], ah[mt][3],
                      Ah + aoff + mt * (16 * APITCH));
                LDSM4(al[mt][0], al[mt][1], al[mt][2], al[mt][3],
                      Al + aoff + mt * (16 * APITCH));
            }
            #pragma unroll
            for (int p = 0; p < 2; ++p) {
                LDSM4(bh[p][0], bh[p][1], bh[p][2], bh[p][3],
                      Bh + boff + p * (16 * APITCH));
                LDSM4(bl[p][0], bl[p][1], bl[p][2], bl[p][3],
                      Bl + boff + p * (16 * APITCH));
            }
            #pragma unroll
            for (int mt = 0; mt < 4; ++mt)
                #pragma unroll
                for (int nt = 0; nt < 4; ++nt) {
                    const int p = nt >> 1, h = (nt & 1) * 2;
                    MMA16816(acc[mt][nt], ah[mt], bh[p][h], bh[p][h + 1]);
                    MMA16816(acc[mt][nt], ah[mt], bl[p][h], bl[p][h + 1]);
                    MMA16816(acc[mt][nt], al[mt], bh[p][h], bh[p][h + 1]);
                }
        }
        __syncthreads();
    }

    // epilogue
    const int erow = lane >> 2, ecol = (lane & 3) * 2;
    #pragma unroll
    for (int mt = 0; mt < 4; ++mt) {
        #pragma unroll
        for (int nt = 0; nt < 4; ++nt) {
            int m0 = tm + wm + mt * 16 + erow;
            int n0 = tn + wn + nt * 8 + ecol;
            float bx = bias[n0], by = bias[n0 + 1];
            if (m0 < MTOT) {
                float2 o;
                o.x = (acc[mt][nt][0] + bx) * scale;
                o.y = (acc[mt][nt][1] + by) * scale;
                *(float2*)(Y + (size_t)m0 * D_ + n0) = o;
            }
            if (m0 + 8 < MTOT) {
                float2 o;
                o.x = (acc[mt][nt][2] + bx) * scale;
                o.y = (acc[mt][nt][3] + by) * scale;
                *(float2*)(Y + (size_t)(m0 + 8) * D_ + n0) = o;
            }
        }
    }
}

// ============================================================================
// xa[b,slot,s,r] = sum_d X[b,s,d] * A[idx[b,slot], r, d]
// Block = (b, slot, rh*8 + schunk): 1024 blocks.
// ============================================================================
__global__ __launch_bounds__(256) void xa_kernel(
    const float* __restrict__ X, const float* __restrict__ A,
    const int* __restrict__ idx, float* __restrict__ xa)
{
    int b = blockIdx.x, slot = blockIdx.y;
    int rh = blockIdx.z >> 3, sc = blockIdx.z & 7;
    int sbase = sc * 33;
    int smax = min(S_, sbase + 33);
    int e = idx[b * KE_ + slot];
    __shared__ float As[8][D_];
    const float* Ap = A + ((size_t)e * R_ + rh * 8) * D_;
    for (int i = threadIdx.x; i < 8 * D_ / 4; i += 256)
        ((float4*)As)[i] = ((const float4*)Ap)[i];
    __syncthreads();

    int w = threadIdx.x >> 5, lane = threadIdx.x & 31;
    for (int s4 = sbase + w * 4; s4 < smax; s4 += 32) {
        float sum[8][4];
        #pragma unroll
        for (int r = 0; r < 8; r++)
            #pragma unroll
            for (int si = 0; si < 4; si++) sum[r][si] = 0.f;

        #pragma unroll 1
        for (int c = 0; c < 8; c++) {
            float4 xv[4];
            #pragma unroll
            for (int si = 0; si < 4; si++) {
                int s = s4 + si;
                xv[si] = (s < S_)
                    ? *(const float4*)(X + ((size_t)b * S_ + s) * D_ + c * 128 + lane * 4)
                    : make_float4(0.f, 0.f, 0.f, 0.f);
            }
            #pragma unroll
            for (int r = 0; r < 8; r++) {
                float4 av = *(const float4*)&As[r][c * 128 + lane * 4];
                #pragma unroll
                for (int si = 0; si < 4; si++)
                    sum[r][si] = fmaf(xv[si].x, av.x,
                                 fmaf(xv[si].y, av.y,
                                 fmaf(xv[si].z, av.z,
                                 fmaf(xv[si].w, av.w, sum[r][si]))));
            }
        }
        #pragma unroll
        for (int r = 0; r < 8; r++)
            #pragma unroll
            for (int si = 0; si < 4; si++) {
                float v = sum[r][si];
                #pragma unroll
                for (int o = 16; o; o >>= 1) v += __shfl_xor_sync(0xffffffffu, v, o);
                int s = s4 + si;
                if (lane == 0 && s < S_)
                    xa[(((size_t)b * KE_ + slot) * S_ + s) * R_ + rh * 8 + r] = v;
            }
    }
}

// ============================================================================
// Y[b,s,c] += scale * sum_slot gate * (xa[b,slot,s,:] . Bm[e, c, :])
// ============================================================================
__global__ __launch_bounds__(256) void lora_add(
    const float* __restrict__ Bm, const int* __restrict__ idx,
    const float* __restrict__ gates, const float* __restrict__ xa,
    float* __restrict__ Y, float scale)
{
    int b = blockIdx.x;
    int cn = blockIdx.y << 6;
    int t = threadIdx.x;
    __shared__ float Bs[2][64][17];
    __shared__ float xs[2][64][17];
    int e0 = idx[b * KE_], e1 = idx[b * KE_ + 1];
    float g0 = gates[b * KE_] * scale, g1 = gates[b * KE_ + 1] * scale;

    for (int i = t; i < 2048; i += 256) {
        int slot = i >> 10, rem = i & 1023, c = rem >> 4, r = rem & 15;
        Bs[slot][c][r] = Bm[((size_t)(slot ? e1 : e0) * D_ + cn + c) * R_ + r];
    }

    int c = t & 63, sq = t >> 6;
    for (int s0 = 0; s0 < S_; s0 += 64) {
        __syncthreads();
        for (int i = t; i < 2048; i += 256) {
            int slot = i >> 10, rem = i & 1023, si = rem >> 4, r = rem & 15;
            int s = s0 + si;
            float v = (s < S_) ? xa[(((size_t)b * KE_ + slot) * S_ + s) * R_ + r] : 0.f;
            xs[slot][si][r] = v * (slot ? g1 : g0);
        }
        __syncthreads();
        for (int si = sq; si < 64; si += 4) {
            int s = s0 + si;
            if (s >= S_) break;
            float sum = 0.f;
            #pragma unroll
            for (int r = 0; r < 16; r++) {
                sum = fmaf(xs[0][si][r], Bs[0][c][r], sum);
                sum = fmaf(xs[1][si][r], Bs[1][c][r], sum);
            }
            Y[((size_t)b * S_ + s) * D_ + cn + c] += sum;
        }
    }
}

// ---------------- scores[bh,s,t] = q[bh,s,:] . k[bh,t,:] -------------------
__global__ __launch_bounds__(256) void attn_scores(
    const float* __restrict__ Q, const float* __restrict__ Kk)
{
    int bh = blockIdx.z; int b = bh >> 4, h = bh & 15;
    int tm = blockIdx.y << 6, tn = blockIdx.x << 6;
    __shared__ float Qs[16][64];
    __shared__ float Ks[16][64];
    int t = threadIdx.x;
    int lrow = t >> 2, lcol = (t & 3) << 2;
    int tx = t & 15, ty = t >> 4;
    float acc[4][4] = {};
    bool qv = (tm + lrow) < S_;
    bool kv = (tn + lrow) < S_;
    const float* Qp = Q + ((size_t)b * S_ + tm + lrow) * D_ + h * HD_ + lcol;
    const float* Kp = Kk + ((size_t)b * S_ + tn + lrow) * D_ + h * HD_ + lcol;

    for (int k0 = 0; k0 < HD_; k0 += 16) {
        float4 qq = qv ? *(const float4*)(Qp + k0) : make_float4(0.f,0.f,0.f,0.f);
        float4 kq = kv ? *(const float4*)(Kp + k0) : make_float4(0.f,0.f,0.f,0.f);
        __syncthreads();
        Qs[lcol  ][lrow] = qq.x; Qs[lcol+1][lrow] = qq.y;
        Qs[lcol+2][lrow] = qq.z; Qs[lcol+3][lrow] = qq.w;
        Ks[lcol  ][lrow] = kq.x; Ks[lcol+1][lrow] = kq.y;
        Ks[lcol+2][lrow] = kq.z; Ks[lcol+3][lrow] = kq.w;
        __syncthreads();
        #pragma unroll
        for (int kk = 0; kk < 16; kk++) {
            float4 kr = *(const float4*)&Ks[kk][tx << 2];
            float kr4[4] = {kr.x, kr.y, kr.z, kr.w};
            float qr[4];
            #pragma unroll
            for (int i = 0; i < 4; i++) qr[i] = Qs[kk][(ty << 2) + i];
            #pragma unroll
            for (int i = 0; i < 4; i++)
                #pragma unroll
                for (int j = 0; j < 4; j++)
                    acc[i][j] = fmaf(qr[i], kr4[j], acc[i][j]);
        }
    }

    float* sp = g_sc + (size_t)bh * S_ * S_;
    #pragma unroll
    for (int i = 0; i < 4; i++) {
        int s = tm + (ty << 2) + i;
        if (s >= S_) break;
        #pragma unroll
        for (int j = 0; j < 4; j++) {
            int tt = tn + (tx << 2) + j;
            if (tt < S_) sp[(size_t)s * S_ + tt] = acc[i][j];
        }
    }
}

// ---------------- row softmax over t (length 257) --------------------------
__global__ __launch_bounds__(256) void softmax_k()
{
    size_t row = blockIdx.x;
    float* p = g_sc + row * S_;
    int t = threadIdx.x;
    float v0 = p[t];
    float v1 = (t == 0) ? p[256] : -1e30f;
    __shared__ float sm[256];
    sm[t] = fmaxf(v0, v1);
    __syncthreads();
    #pragma unroll
    for (int o = 128; o; o >>= 1) {
        if (t < o) sm[t] = fmaxf(sm[t], sm[t + o]);
        __syncthreads();
    }
    float rmax = sm[0];
    __syncthreads();
    float e0 = __expf(v0 - rmax);
    float e1 = (t == 0) ? __expf(v1 - rmax) : 0.f;
    sm[t] = e0 + e1;
    __syncthreads();
    #pragma unroll
    for (int o = 128; o; o >>= 1) {
        if (t < o) sm[t] += sm[t + o];
        __syncthreads();
    }
    float inv = 1.f / sm[0];
    p[t] = e0 * inv;
    if (t == 0) p[256] = e1 * inv;
}

// ---------------- out[bh,s,d] = sum_t attn[s,t] * v[bh,t,d] ----------------
__global__ __launch_bounds__(256) void attn_av(
    const float* __restrict__ V, float* __restrict__ Xo)
{
    int bh = blockIdx.z; int b = bh >> 4, h = bh & 15;
    int tm = blockIdx.y << 6;
    __shared__ float As[16][64];
    __shared__ float Vs[16][64];
    int t = threadIdx.x;
    int arow = t >> 2, acol = (t & 3) << 2;
    int vrow = t >> 4, vcol = (t & 15) << 2;
    int tx = t & 15, ty = t >> 4;
    float acc[4][4] = {};
    const float* sp = g_sc + (size_t)bh * S_ * S_;

    for (int k0 = 0; k0 < S_; k0 += 16) {
        int srow = tm + arow;
        bool sv = srow < S_;
        const float* ap = sp + (size_t)srow * S_ + k0 + acol;
        float a0 = (sv && (k0 + acol + 0) < S_) ? ap[0] : 0.f;
        float a1 = (sv && (k0 + acol + 1) < S_) ? ap[1] : 0.f;
        float a2 = (sv && (k0 + acol + 2) < S_) ? ap[2] : 0.f;
        float a3 = (sv && (k0 + acol + 3) < S_) ? ap[3] : 0.f;
        bool vv = (k0 + vrow) < S_;
        float4 vq = vv ? *(const float4*)(V + ((size_t)b * S_ + k0 + vrow) * D_ + h * HD_ + vcol)
                       : make_float4(0.f, 0.f, 0.f, 0.f);
        __syncthreads();
        As[acol  ][arow] = a0; As[acol+1][arow] = a1;
        As[acol+2][arow] = a2; As[acol+3][arow] = a3;
        Vs[vrow][vcol  ] = vq.x; Vs[vrow][vcol+1] = vq.y;
        Vs[vrow][vcol+2] = vq.z; Vs[vrow][vcol+3] = vq.w;
        __syncthreads();
        #pragma unroll
        for (int kk = 0; kk < 16; kk++) {
            float4 vr = *(const float4*)&Vs[kk][tx << 2];
            float vr4[4] = {vr.x, vr.y, vr.z, vr.w};
            float ar[4];
            #pragma unroll
            for (int i = 0; i < 4; i++) ar[i] = As[kk][(ty << 2) + i];
            #pragma unroll
            for (int i = 0; i < 4; i++)
                #pragma unroll
                for (int j = 0; j < 4; j++)
                    acc[i][j] = fmaf(ar[i], vr4[j], acc[i][j]);
        }
    }

    #pragma unroll
    for (int i = 0; i < 4; i++) {
        int s = tm + (ty << 2) + i;
        if (s >= S_) break;
        float* op = Xo + ((size_t)b * S_ + s) * D_ + h * HD_ + (tx << 2);
        #pragma unroll
        for (int j = 0; j < 4; j++) op[j] = acc[i][j];
    }
}

// ---------------- host launcher --------------------------------------------
extern "C" void kernel_launch(void* const* d_in, const int* in_sizes, int n_in,
                              void* d_out, int out_size)
{
    const float* hs    = (const float*)d_in[0];
    const int*   idx   = (const int*)  d_in[1];
    const float* gates = (const float*)d_in[2];
    const float* wq = (const float*)d_in[3];  const float* Aq = (const float*)d_in[4];
    const float* Bq = (const float*)d_in[5];  const float* bq = (const float*)d_in[6];
    const float* wk = (const float*)d_in[7];  const float* Ak = (const float*)d_in[8];
    const float* Bk = (const float*)d_in[9];  const float* bk = (const float*)d_in[10];
    const float* wv = (const float*)d_in[11]; const float* Av = (const float*)d_in[12];
    const float* Bv = (const float*)d_in[13]; const float* bv = (const float*)d_in[14];
    const float* wo = (const float*)d_in[15]; const float* Ao = (const float*)d_in[16];
    const float* Bo = (const float*)d_in[17]; const float* bo = (const float*)d_in[18];
    float* out = (float*)d_out;

    float *q, *k, *v, *x2, *xa;
    __nv_bfloat16 *xhi, *xlo, *whi, *wlo;
    cudaGetSymbolAddress((void**)&q,   g_q);
    cudaGetSymbolAddress((void**)&k,   g_k);
    cudaGetSymbolAddress((void**)&v,   g_v);
    cudaGetSymbolAddress((void**)&x2,  g_x2);
    cudaGetSymbolAddress((void**)&xa,  g_xa);
    cudaGetSymbolAddress((void**)&xhi, g_xhi);
    cudaGetSymbolAddress((void**)&xlo, g_xlo);
    cudaGetSymbolAddress((void**)&whi, g_whi);
    cudaGetSymbolAddress((void**)&wlo, g_wlo);

    cudaFuncSetAttribute(mma_gemm, cudaFuncAttributeMaxDynamicSharedMemorySize, GEMM_SMEM);

    const int nx4 = MTOT * D_ / 4;
    const int nw4 = D_ * D_ / 4;
    dim3 gx(B_, KE_, 16);
    dim3 gt(D_ / 128, (MTOT + 127) / 128);   // 8 x 65
    dim3 gl(B_, D_ / 64);                    // 32 x 16

    split_bf16<<<(nx4 + 255) / 256, 256>>>((const float4*)hs, (uint2*)xhi, (uint2*)xlo, nx4);

    // Q
    xa_kernel<<<gx, 256>>>(hs, Aq, idx, xa);
    split_bf16<<<(nw4 + 255) / 256, 256>>>((const float4*)wq, (uint2*)whi, (uint2*)wlo, nw4);
    mma_gemm<<<gt, 256, GEMM_SMEM>>>(xhi, xlo, whi, wlo, bq, q, SCALE_Q);
    lora_add<<<gl, 256>>>(Bq, idx, gates, xa, q, SCALE_Q);
    // K
    xa_kernel<<<gx, 256>>>(hs, Ak, idx, xa);
    split_bf16<<<(nw4 + 255) / 256, 256>>>((const float4*)wk, (uint2*)whi, (uint2*)wlo, nw4);
    mma_gemm<<<gt, 256, GEMM_SMEM>>>(xhi, xlo, whi, wlo, bk, k, 1.f);
    lora_add<<<gl, 256>>>(Bk, idx, gates, xa, k, 1.f);
    // V
    xa_kernel<<<gx, 256>>>(hs, Av, idx, xa);
    split_bf16<<<(nw4 + 255) / 256, 256>>>((const float4*)wv, (uint2*)whi, (uint2*)wlo, nw4);
    mma_gemm<<<gt, 256, GEMM_SMEM>>>(xhi, xlo, whi, wlo, bv, v, 1.f);
    lora_add<<<gl, 256>>>(Bv, idx, gates, xa, v, 1.f);

    attn_scores<<<dim3(5, 5, B_ * H_), 256>>>(q, k);
    softmax_k<<<B_ * H_ * S_, 256>>>();
    attn_av<<<dim3(1, 5, B_ * H_), 256>>>(v, x2);

    // O
    xa_kernel<<<gx, 256>>>(x2, Ao, idx, xa);
    split_bf16<<<(nx4 + 255) / 256, 256>>>((const float4*)x2, (uint2*)xhi, (uint2*)xlo, nx4);
    split_bf16<<<(nw4 + 255) / 256, 256>>>((const float4*)wo, (uint2*)whi, (uint2*)wlo, nw4);
    mma_gemm<<<gt, 256, GEMM_SMEM>>>(xhi, xlo, whi, wlo, bo, out, 1.f);
    lora_add<<<gl, 256>>>(Bo, idx, gates, xa, out, 1.f);
}

// round 6
// speedup vs baseline: 3.5296x; 1.3087x over previous
#include <cuda_runtime.h>
#include <cuda_bf16.h>
#include <cstdint>

#define B_ 32
#define S_ 257
#define D_ 1024
#define H_ 16
#define HD_ 64
#define E_ 8
#define R_ 16
#define KE_ 2
#define MTOT (B_*S_)
#define SCALE_Q 0.125f

// ---------------- scratch (device globals: allocation-free) ----------------
__device__ float g_tmp[(size_t)MTOT * D_];
__device__ float g_x2 [(size_t)MTOT * D_];
__device__ float g_xa [(size_t)B_ * KE_ * S_ * R_];
__device__ __nv_bfloat16 g_xhi[(size_t)MTOT * D_];
__device__ __nv_bfloat16 g_xlo[(size_t)MTOT * D_];
__device__ __nv_bfloat16 g_whi[(size_t)D_ * D_];
__device__ __nv_bfloat16 g_wlo[(size_t)D_ * D_];
__device__ __nv_bfloat16 g_qhi[(size_t)MTOT * D_];
__device__ __nv_bfloat16 g_qlo[(size_t)MTOT * D_];
__device__ __nv_bfloat16 g_khi[(size_t)MTOT * D_];
__device__ __nv_bfloat16 g_klo[(size_t)MTOT * D_];
__device__ __nv_bfloat16 g_vhi[(size_t)MTOT * D_];
__device__ __nv_bfloat16 g_vlo[(size_t)MTOT * D_];

// ========================= helpers (baseline PTX only) ======================
__device__ __forceinline__ uint32_t smem_u32(const void* p) {
    uint32_t a;
    asm("{ .reg .u64 t; cvta.to.shared.u64 t, %1; cvt.u32.u64 %0, t; }"
        : "=r"(a) : "l"(p));
    return a;
}

#define LDSM4(r0, r1, r2, r3, addr) \
    asm volatile("ldmatrix.sync.aligned.m8n8.x4.shared.b16 {%0,%1,%2,%3}, [%4];" \
        : "=r"(r0), "=r"(r1), "=r"(r2), "=r"(r3) : "r"(addr))

#define LDSM4T(r0, r1, r2, r3, addr) \
    asm volatile("ldmatrix.sync.aligned.m8n8.x4.trans.shared.b16 {%0,%1,%2,%3}, [%4];" \
        : "=r"(r0), "=r"(r1), "=r"(r2), "=r"(r3) : "r"(addr))

#define MMA16816(d, a, b0, b1) \
    asm volatile("mma.sync.aligned.m16n8k16.row.col.f32.bf16.bf16.f32 " \
        "{%0,%1,%2,%3}, {%4,%5,%6,%7}, {%8,%9}, {%0,%1,%2,%3};" \
        : "+f"((d)[0]), "+f"((d)[1]), "+f"((d)[2]), "+f"((d)[3]) \
        : "r"((a)[0]), "r"((a)[1]), "r"((a)[2]), "r"((a)[3]), "r"(b0), "r"(b1))

#define CP_ASYNC16(dst, src, sz) \
    asm volatile("cp.async.cg.shared.global [%0], [%1], 16, %2;" \
        :: "r"(dst), "l"(src), "r"(sz))
#define CP_COMMIT()  asm volatile("cp.async.commit_group;" ::: "memory")
#define CP_WAIT1()   asm volatile("cp.async.wait_group 1;" ::: "memory")
#define CP_WAIT0()   asm volatile("cp.async.wait_group 0;" ::: "memory")

// fast exp on FMA pipe: x <= 0 expected; clamped; rel err ~2e-6
__device__ __forceinline__ float fexp(float x) {
    x = fmaxf(x, -80.f);
    float t = x * 1.4426950408889634f;
    float z = t + 12582912.f;
    int   k = __float_as_int(z) - 0x4B400000;
    float f = t - (z - 12582912.f);
    float p = 1.3333558146428443e-3f;
    p = fmaf(p, f, 9.6181291076284772e-3f);
    p = fmaf(p, f, 5.5504108664821580e-2f);
    p = fmaf(p, f, 2.4022650695910071e-1f);
    p = fmaf(p, f, 6.9314718055994531e-1f);
    p = fmaf(p, f, 1.0f);
    return __int_as_float(__float_as_int(p) + (k << 23));
}

// ============================================================================
// split fp32 -> (bf16 hi, bf16 lo) with lo = bf16(x - hi)
// ============================================================================
__global__ __launch_bounds__(256) void split_bf16(
    const float4* __restrict__ x, uint2* __restrict__ hi, uint2* __restrict__ lo, int n4)
{
    int i = blockIdx.x * 256 + threadIdx.x;
    if (i >= n4) return;
    float4 v = x[i];
    __nv_bfloat162 h01 = __floats2bfloat162_rn(v.x, v.y);
    __nv_bfloat162 h23 = __floats2bfloat162_rn(v.z, v.w);
    float lx = v.x - __bfloat162float(h01.x);
    float ly = v.y - __bfloat162float(h01.y);
    float lz = v.z - __bfloat162float(h23.x);
    float lw = v.w - __bfloat162float(h23.y);
    __nv_bfloat162 l01 = __floats2bfloat162_rn(lx, ly);
    __nv_bfloat162 l23 = __floats2bfloat162_rn(lz, lw);
    uint2 hv, lv;
    hv.x = *(uint32_t*)&h01; hv.y = *(uint32_t*)&h23;
    lv.x = *(uint32_t*)&l01; lv.y = *(uint32_t*)&l23;
    hi[i] = hv; lo[i] = lv;
}

// ============================================================================
// HMMA GEMM: Y = (Xf32 @ Wf32^T + bias) * scale   via bf16x3 split
// ============================================================================
#define APITCH 80
#define TILEB (128 * APITCH)
#define STAGEB (4 * TILEB)
#define GEMM_SMEM (2 * STAGEB)

__device__ __forceinline__ void stage_load(
    uint32_t sb, int buf, int c, int tm, int tn, int tid,
    const __nv_bfloat16* __restrict__ Xhi, const __nv_bfloat16* __restrict__ Xlo,
    const __nv_bfloat16* __restrict__ Whi, const __nv_bfloat16* __restrict__ Wlo)
{
    uint32_t st = sb + buf * STAGEB;
    #pragma unroll
    for (int j = 0; j < 8; ++j) {
        int g = tid + j * 256;
        int tile = g >> 9, i = g & 511, row = i >> 2, seg = i & 3;
        const __nv_bfloat16* base = (tile == 0) ? Xhi : (tile == 1) ? Xlo
                                   : (tile == 2) ? Whi : Wlo;
        int grow = ((tile < 2) ? tm : tn) + row;
        const void* src = base + (size_t)grow * D_ + c * 32 + seg * 8;
        uint32_t dst = st + tile * TILEB + row * APITCH + seg * 16;
        int sz = (tile >= 2 || grow < MTOT) ? 16 : 0;
        CP_ASYNC16(dst, src, sz);
    }
}

__global__ __launch_bounds__(256) void mma_gemm(
    const __nv_bfloat16* __restrict__ Xhi, const __nv_bfloat16* __restrict__ Xlo,
    const __nv_bfloat16* __restrict__ Whi, const __nv_bfloat16* __restrict__ Wlo,
    const float* __restrict__ bias, float* __restrict__ Y, float scale)
{
    extern __shared__ char smem[];
    const uint32_t sb = smem_u32(smem);
    const int tid = threadIdx.x;
    const int wid = tid >> 5, lane = tid & 31;
    const int tm = blockIdx.y << 7, tn = blockIdx.x << 7;
    const int wm = (wid & 1) * 64, wn = (wid >> 1) * 32;

    const int lrow = lane & 15;
    const int lk   = lane >> 4;
    const int brow = ((lane >> 4) << 3) + (lane & 7);
    const int bk   = (lane >> 3) & 1;

    float acc[4][4][4] = {};

    stage_load(sb, 0, 0, tm, tn, tid, Xhi, Xlo, Whi, Wlo);
    CP_COMMIT();

    for (int c = 0; c < 32; ++c) {
        const int buf = c & 1;
        if (c + 1 < 32) {
            stage_load(sb, buf ^ 1, c + 1, tm, tn, tid, Xhi, Xlo, Whi, Wlo);
            CP_COMMIT();
            CP_WAIT1();
        } else {
            CP_WAIT0();
        }
        __syncthreads();

        const uint32_t Ah = sb + buf * STAGEB;
        const uint32_t Al = Ah + TILEB;
        const uint32_t Bh = Ah + 2 * TILEB;
        const uint32_t Bl = Ah + 3 * TILEB;

        #pragma unroll
        for (int kk2 = 0; kk2 < 2; ++kk2) {
            const int kkb = kk2 * 32;
            uint32_t ah[4][4], al[4][4], bh[2][4], bl[2][4];
            const uint32_t aoff = (uint32_t)(wm + lrow) * APITCH + kkb + lk * 16;
            const uint32_t boff = (uint32_t)(wn + brow) * APITCH + kkb + bk * 16;
            #pragma unroll
            for (int mt = 0; mt < 4; ++mt) {
                LDSM4(ah[mt][0], ah[mt][1], ah[mt][2], ah[mt][3],
                      Ah + aoff + mt * (16 * APITCH));
                LDSM4(al[mt][0], al[mt][1], al[mt][2], al[mt][3],
                      Al + aoff + mt * (16 * APITCH));
            }
            #pragma unroll
            for (int p = 0; p < 2; ++p) {
                LDSM4(bh[p][0], bh[p][1], bh[p][2], bh[p][3],
                      Bh + boff + p * (16 * APITCH));
                LDSM4(bl[p][0], bl[p][1], bl[p][2], bl[p][3],
                      Bl + boff + p * (16 * APITCH));
            }
            #pragma unroll
            for (int mt = 0; mt < 4; ++mt)
                #pragma unroll
                for (int nt = 0; nt < 4; ++nt) {
                    const int p = nt >> 1, h = (nt & 1) * 2;
                    MMA16816(acc[mt][nt], ah[mt], bh[p][h], bh[p][h + 1]);
                    MMA16816(acc[mt][nt], ah[mt], bl[p][h], bl[p][h + 1]);
                    MMA16816(acc[mt][nt], al[mt], bh[p][h], bh[p][h + 1]);
                }
        }
        __syncthreads();
    }

    const int erow = lane >> 2, ecol = (lane & 3) * 2;
    #pragma unroll
    for (int mt = 0; mt < 4; ++mt) {
        #pragma unroll
        for (int nt = 0; nt < 4; ++nt) {
            int m0 = tm + wm + mt * 16 + erow;
            int n0 = tn + wn + nt * 8 + ecol;
            float bx = bias[n0], by = bias[n0 + 1];
            if (m0 < MTOT) {
                float2 o;
                o.x = (acc[mt][nt][0] + bx) * scale;
                o.y = (acc[mt][nt][1] + by) * scale;
                *(float2*)(Y + (size_t)m0 * D_ + n0) = o;
            }
            if (m0 + 8 < MTOT) {
                float2 o;
                o.x = (acc[mt][nt][2] + bx) * scale;
                o.y = (acc[mt][nt][3] + by) * scale;
                *(float2*)(Y + (size_t)(m0 + 8) * D_ + n0) = o;
            }
        }
    }
}

// ============================================================================
// Fused flash attention: out[b,h,s,:] = softmax(q k^T) v   (q pre-scaled)
// grid (BH=512, MT=3), 256 thr. Q frags in regs; KV 64-row tiles double-buf.
// scores & PV both bf16x3 HMMA; softmax in regs with poly exp.
// ============================================================================
#define FPITCH 144
#define KVROWB (64 * FPITCH)            // 9216 bytes per tensor-half tile
#define KVSTG  (4 * KVROWB)             // khi,klo,vhi,vlo = 36864
#define FA_SMEM (2 * KVSTG)

__device__ __forceinline__ void load_kv(
    uint32_t st, int t0, size_t kvbase, int tid,
    const __nv_bfloat16* __restrict__ khi, const __nv_bfloat16* __restrict__ klo,
    const __nv_bfloat16* __restrict__ vhi, const __nv_bfloat16* __restrict__ vlo)
{
    #pragma unroll
    for (int j = 0; j < 8; ++j) {
        int g = tid + j * 256;
        int tens = g >> 9, i = g & 511, row = i >> 3, seg = i & 7;
        const __nv_bfloat16* bp = (tens == 0) ? khi : (tens == 1) ? klo
                                 : (tens == 2) ? vhi : vlo;
        const void* src = bp + kvbase + (size_t)(t0 + row) * D_ + seg * 8;
        uint32_t dst = st + tens * KVROWB + row * FPITCH + seg * 16;
        CP_ASYNC16(dst, src, (t0 + row) < S_ ? 16 : 0);
    }
}

__global__ __launch_bounds__(256, 1) void flash_attn(
    const __nv_bfloat16* __restrict__ qhi, const __nv_bfloat16* __restrict__ qlo,
    const __nv_bfloat16* __restrict__ khi, const __nv_bfloat16* __restrict__ klo,
    const __nv_bfloat16* __restrict__ vhi, const __nv_bfloat16* __restrict__ vlo,
    float* __restrict__ Xo)
{
    extern __shared__ char smem[];
    const uint32_t sb = smem_u32(smem);
    const int tid = threadIdx.x, wid = tid >> 5, lane = tid & 31;
    const int bh = blockIdx.x, b = bh >> 4, h = bh & 15;
    const int m0 = blockIdx.y * 128;
    const size_t kvbase = (size_t)b * S_ * D_ + h * HD_;

    // ---- stage Q tile (hi -> stage0, lo -> stage1), move to registers
    #pragma unroll
    for (int j = 0; j < 8; ++j) {
        int g = tid + j * 256;
        int half = g >> 10, i = g & 1023, row = i >> 3, seg = i & 7;
        const __nv_bfloat16* src = (half ? qlo : qhi) + kvbase
                                 + (size_t)(m0 + row) * D_ + seg * 8;
        uint32_t dst = sb + half * KVSTG + row * FPITCH + seg * 16;
        CP_ASYNC16(dst, src, (m0 + row) < S_ ? 16 : 0);
    }
    CP_COMMIT(); CP_WAIT0();
    __syncthreads();

    uint32_t qh[4][4], ql[4][4];
    {
        const uint32_t base = sb + (uint32_t)(wid * 16 + (lane & 15)) * FPITCH
                            + (lane >> 4) * 16;
        #pragma unroll
        for (int kk = 0; kk < 4; ++kk) {
            LDSM4(qh[kk][0], qh[kk][1], qh[kk][2], qh[kk][3], base + kk * 32);
            LDSM4(ql[kk][0], ql[kk][1], ql[kk][2], ql[kk][3], base + KVSTG + kk * 32);
        }
    }
    __syncthreads();

    float acc_o[8][4] = {};
    float mrow[2] = {-1e30f, -1e30f}, lrow[2] = {0.f, 0.f};
    const int brow = ((lane >> 4) << 3) + (lane & 7);
    const int bk   = (lane >> 3) & 1;
    const int quad = lane & 3;

    load_kv(sb, 0, kvbase, tid, khi, klo, vhi, vlo);
    CP_COMMIT();

    #pragma unroll 1
    for (int kv = 0; kv < 5; ++kv) {
        CP_WAIT0();
        __syncthreads();
        const uint32_t Ks = sb + (kv & 1) * KVSTG;
        const uint32_t Vs = Ks + 2 * KVROWB;
        if (kv < 4) {
            load_kv(sb + ((kv + 1) & 1) * KVSTG, (kv + 1) * 64, kvbase, tid,
                    khi, klo, vhi, vlo);
            CP_COMMIT();
        }

        // ---- scores S = q k^T (bf16x3)
        float s[8][4] = {};
        #pragma unroll
        for (int kk = 0; kk < 4; ++kk) {
            #pragma unroll
            for (int p = 0; p < 4; ++p) {
                uint32_t kh0, kh1, kh2, kh3, kl0, kl1, kl2, kl3;
                uint32_t ko = Ks + (uint32_t)(p * 16 + brow) * FPITCH + kk * 32 + bk * 16;
                LDSM4(kh0, kh1, kh2, kh3, ko);
                LDSM4(kl0, kl1, kl2, kl3, ko + KVROWB);
                MMA16816(s[2*p],   qh[kk], kh0, kh1);
                MMA16816(s[2*p],   qh[kk], kl0, kl1);
                MMA16816(s[2*p],   ql[kk], kh0, kh1);
                MMA16816(s[2*p+1], qh[kk], kh2, kh3);
                MMA16816(s[2*p+1], qh[kk], kl2, kl3);
                MMA16816(s[2*p+1], ql[kk], kh2, kh3);
            }
        }

        // ---- mask tail (kv tile 4 has only t=256 valid)
        if (kv == 4) {
            #pragma unroll
            for (int nt = 0; nt < 8; ++nt)
                #pragma unroll
                for (int rg = 0; rg < 4; ++rg) {
                    int col = 256 + nt * 8 + quad * 2 + (rg & 1);
                    if (col >= S_) s[nt][rg] = -1e30f;
                }
        }

        // ---- online softmax (rows: rr=0 -> lane>>2, rr=1 -> +8)
        #pragma unroll
        for (int rr = 0; rr < 2; ++rr) {
            float mx = -1e30f;
            #pragma unroll
            for (int nt = 0; nt < 8; ++nt)
                mx = fmaxf(mx, fmaxf(s[nt][2*rr], s[nt][2*rr+1]));
            mx = fmaxf(mx, __shfl_xor_sync(0xffffffffu, mx, 1));
            mx = fmaxf(mx, __shfl_xor_sync(0xffffffffu, mx, 2));
            float mnew = fmaxf(mrow[rr], mx);
            float alpha = fexp(mrow[rr] - mnew);
            mrow[rr] = mnew;
            float sum = 0.f;
            #pragma unroll
            for (int nt = 0; nt < 8; ++nt) {
                float p0 = fexp(s[nt][2*rr]   - mnew);
                float p1 = fexp(s[nt][2*rr+1] - mnew);
                s[nt][2*rr] = p0; s[nt][2*rr+1] = p1;
                sum += p0 + p1;
            }
            sum += __shfl_xor_sync(0xffffffffu, sum, 1);
            sum += __shfl_xor_sync(0xffffffffu, sum, 2);
            lrow[rr] = lrow[rr] * alpha + sum;
            #pragma unroll
            for (int nt = 0; nt < 8; ++nt) {
                acc_o[nt][2*rr]   *= alpha;
                acc_o[nt][2*rr+1] *= alpha;
            }
        }

        // ---- out += P V (bf16x2 split of P, bf16x3 product)
        #pragma unroll
        for (int kk = 0; kk < 4; ++kk) {
            uint32_t ph[4], pl[4];
            #pragma unroll
            for (int rg = 0; rg < 4; ++rg) {
                int nt = 2 * kk + (rg >> 1);
                float p0 = s[nt][(rg & 1) * 2];
                float p1 = s[nt][(rg & 1) * 2 + 1];
                __nv_bfloat162 hb = __floats2bfloat162_rn(p0, p1);
                float l0 = p0 - __bfloat162float(hb.x);
                float l1 = p1 - __bfloat162float(hb.y);
                __nv_bfloat162 lb = __floats2bfloat162_rn(l0, l1);
                ph[rg] = *(uint32_t*)&hb;
                pl[rg] = *(uint32_t*)&lb;
            }
            #pragma unroll
            for (int p = 0; p < 4; ++p) {
                uint32_t vh0, vh1, vh2, vh3, vl0, vl1, vl2, vl3;
                uint32_t vo = Vs + (uint32_t)(kk * 16 + (lane & 15)) * FPITCH
                            + p * 32 + (lane >> 4) * 16;
                LDSM4T(vh0, vh1, vh2, vh3, vo);
                LDSM4T(vl0, vl1, vl2, vl3, vo + KVROWB);
                MMA16816(acc_o[2*p],   ph, vh0, vh1);
                MMA16816(acc_o[2*p],   ph, vl0, vl1);
                MMA16816(acc_o[2*p],   pl, vh0, vh1);
                MMA16816(acc_o[2*p+1], ph, vh2, vh3);
                MMA16816(acc_o[2*p+1], ph, vl2, vl3);
                MMA16816(acc_o[2*p+1], pl, vh2, vh3);
            }
        }
    }

    // ---- epilogue
    {
        const int r = lane >> 2, q2 = quad * 2;
        #pragma unroll
        for (int rr = 0; rr < 2; ++rr) {
            int m = m0 + wid * 16 + r + rr * 8;
            if (m < S_) {
                float inv = 1.f / lrow[rr];
                float* op = Xo + ((size_t)b * S_ + m) * D_ + h * HD_ + q2;
                #pragma unroll
                for (int nt = 0; nt < 8; ++nt) {
                    float2 o;
                    o.x = acc_o[nt][2*rr]   * inv;
                    o.y = acc_o[nt][2*rr+1] * inv;
                    *(float2*)(op + nt * 8) = o;
                }
            }
        }
    }
}

// ============================================================================
// xa[b,slot,s,r] = sum_d X[b,s,d] * A[idx[b,slot], r, d]
// ============================================================================
__global__ __launch_bounds__(256) void xa_kernel(
    const float* __restrict__ X, const float* __restrict__ A,
    const int* __restrict__ idx, float* __restrict__ xa)
{
    int b = blockIdx.x, slot = blockIdx.y;
    int rh = blockIdx.z >> 3, sc = blockIdx.z & 7;
    int sbase = sc * 33;
    int smax = min(S_, sbase + 33);
    int e = idx[b * KE_ + slot];
    __shared__ float As[8][D_];
    const float* Ap = A + ((size_t)e * R_ + rh * 8) * D_;
    for (int i = threadIdx.x; i < 8 * D_ / 4; i += 256)
        ((float4*)As)[i] = ((const float4*)Ap)[i];
    __syncthreads();

    int w = threadIdx.x >> 5, lane = threadIdx.x & 31;
    for (int s4 = sbase + w * 4; s4 < smax; s4 += 32) {
        float sum[8][4];
        #pragma unroll
        for (int r = 0; r < 8; r++)
            #pragma unroll
            for (int si = 0; si < 4; si++) sum[r][si] = 0.f;

        #pragma unroll 1
        for (int c = 0; c < 8; c++) {
            float4 xv[4];
            #pragma unroll
            for (int si = 0; si < 4; si++) {
                int s = s4 + si;
                xv[si] = (s < S_)
                    ? *(const float4*)(X + ((size_t)b * S_ + s) * D_ + c * 128 + lane * 4)
                    : make_float4(0.f, 0.f, 0.f, 0.f);
            }
            #pragma unroll
            for (int r = 0; r < 8; r++) {
                float4 av = *(const float4*)&As[r][c * 128 + lane * 4];
                #pragma unroll
                for (int si = 0; si < 4; si++)
                    sum[r][si] = fmaf(xv[si].x, av.x,
                                 fmaf(xv[si].y, av.y,
                                 fmaf(xv[si].z, av.z,
                                 fmaf(xv[si].w, av.w, sum[r][si]))));
            }
        }
        #pragma unroll
        for (int r = 0; r < 8; r++)
            #pragma unroll
            for (int si = 0; si < 4; si++) {
                float v = sum[r][si];
                #pragma unroll
                for (int o = 16; o; o >>= 1) v += __shfl_xor_sync(0xffffffffu, v, o);
                int s = s4 + si;
                if (lane == 0 && s < S_)
                    xa[(((size_t)b * KE_ + slot) * S_ + s) * R_ + rh * 8 + r] = v;
            }
    }
}

// ============================================================================
// lora_add: Y += gated LoRA (fp32, for the O projection)
// ============================================================================
__global__ __launch_bounds__(256) void lora_add(
    const float* __restrict__ Bm, const int* __restrict__ idx,
    const float* __restrict__ gates, const float* __restrict__ xa,
    float* __restrict__ Y, float scale)
{
    int b = blockIdx.x;
    int cn = blockIdx.y << 6;
    int t = threadIdx.x;
    __shared__ float Bs[2][64][17];
    __shared__ float xs[2][64][17];
    int e0 = idx[b * KE_], e1 = idx[b * KE_ + 1];
    float g0 = gates[b * KE_] * scale, g1 = gates[b * KE_ + 1] * scale;

    for (int i = t; i < 2048; i += 256) {
        int slot = i >> 10, rem = i & 1023, c = rem >> 4, r = rem & 15;
        Bs[slot][c][r] = Bm[((size_t)(slot ? e1 : e0) * D_ + cn + c) * R_ + r];
    }

    int c = t & 63, sq = t >> 6;
    for (int s0 = 0; s0 < S_; s0 += 64) {
        __syncthreads();
        for (int i = t; i < 2048; i += 256) {
            int slot = i >> 10, rem = i & 1023, si = rem >> 4, r = rem & 15;
            int s = s0 + si;
            float v = (s < S_) ? xa[(((size_t)b * KE_ + slot) * S_ + s) * R_ + r] : 0.f;
            xs[slot][si][r] = v * (slot ? g1 : g0);
        }
        __syncthreads();
        for (int si = sq; si < 64; si += 4) {
            int s = s0 + si;
            if (s >= S_) break;
            float sum = 0.f;
            #pragma unroll
            for (int r = 0; r < 16; r++) {
                sum = fmaf(xs[0][si][r], Bs[0][c][r], sum);
                sum = fmaf(xs[1][si][r], Bs[1][c][r], sum);
            }
            Y[((size_t)b * S_ + s) * D_ + cn + c] += sum;
        }
    }
}

// ============================================================================
// lora_split: out = Yin + gated LoRA, written as bf16 hi/lo split (q/k/v)
// ============================================================================
__global__ __launch_bounds__(256) void lora_split(
    const float* __restrict__ Bm, const int* __restrict__ idx,
    const float* __restrict__ gates, const float* __restrict__ xa,
    const float* __restrict__ Yin,
    __nv_bfloat16* __restrict__ Yhi, __nv_bfloat16* __restrict__ Ylo, float scale)
{
    int b = blockIdx.x;
    int cn = blockIdx.y << 6;
    int t = threadIdx.x;
    __shared__ float Bs[2][64][17];
    __shared__ float xs[2][64][17];
    int e0 = idx[b * KE_], e1 = idx[b * KE_ + 1];
    float g0 = gates[b * KE_] * scale, g1 = gates[b * KE_ + 1] * scale;

    for (int i = t; i < 2048; i += 256) {
        int slot = i >> 10, rem = i & 1023, c = rem >> 4, r = rem & 15;
        Bs[slot][c][r] = Bm[((size_t)(slot ? e1 : e0) * D_ + cn + c) * R_ + r];
    }

    int c = t & 63, sq = t >> 6;
    for (int s0 = 0; s0 < S_; s0 += 64) {
        __syncthreads();
        for (int i = t; i < 2048; i += 256) {
            int slot = i >> 10, rem = i & 1023, si = rem >> 4, r = rem & 15;
            int s = s0 + si;
            float v = (s < S_) ? xa[(((size_t)b * KE_ + slot) * S_ + s) * R_ + r] : 0.f;
            xs[slot][si][r] = v * (slot ? g1 : g0);
        }
        __syncthreads();
        for (int si = sq; si < 64; si += 4) {
            int s = s0 + si;
            if (s >= S_) break;
            float sum = 0.f;
            #pragma unroll
            for (int r = 0; r < 16; r++) {
                sum = fmaf(xs[0][si][r], Bs[0][c][r], sum);
                sum = fmaf(xs[1][si][r], Bs[1][c][r], sum);
            }
            size_t off = ((size_t)b * S_ + s) * D_ + cn + c;
            float v = Yin[off] + sum;
            __nv_bfloat16 hb = __float2bfloat16(v);
            Yhi[off] = hb;
            Ylo[off] = __float2bfloat16(v - __bfloat162float(hb));
        }
    }
}

// ---------------- host launcher --------------------------------------------
extern "C" void kernel_launch(void* const* d_in, const int* in_sizes, int n_in,
                              void* d_out, int out_size)
{
    const float* hs    = (const float*)d_in[0];
    const int*   idx   = (const int*)  d_in[1];
    const float* gates = (const float*)d_in[2];
    const float* wq = (const float*)d_in[3];  const float* Aq = (const float*)d_in[4];
    const float* Bq = (const float*)d_in[5];  const float* bq = (const float*)d_in[6];
    const float* wk = (const float*)d_in[7];  const float* Ak = (const float*)d_in[8];
    const float* Bk = (const float*)d_in[9];  const float* bk = (const float*)d_in[10];
    const float* wv = (const float*)d_in[11]; const float* Av = (const float*)d_in[12];
    const float* Bv = (const float*)d_in[13]; const float* bv = (const float*)d_in[14];
    const float* wo = (const float*)d_in[15]; const float* Ao = (const float*)d_in[16];
    const float* Bo = (const float*)d_in[17]; const float* bo = (const float*)d_in[18];
    float* out = (float*)d_out;

    float *tmp, *x2, *xa;
    __nv_bfloat16 *xhi, *xlo, *whi, *wlo, *qhi, *qlo, *khi, *klo, *vhi, *vlo;
    cudaGetSymbolAddress((void**)&tmp, g_tmp);
    cudaGetSymbolAddress((void**)&x2,  g_x2);
    cudaGetSymbolAddress((void**)&xa,  g_xa);
    cudaGetSymbolAddress((void**)&xhi, g_xhi);
    cudaGetSymbolAddress((void**)&xlo, g_xlo);
    cudaGetSymbolAddress((void**)&whi, g_whi);
    cudaGetSymbolAddress((void**)&wlo, g_wlo);
    cudaGetSymbolAddress((void**)&qhi, g_qhi);
    cudaGetSymbolAddress((void**)&qlo, g_qlo);
    cudaGetSymbolAddress((void**)&khi, g_khi);
    cudaGetSymbolAddress((void**)&klo, g_klo);
    cudaGetSymbolAddress((void**)&vhi, g_vhi);
    cudaGetSymbolAddress((void**)&vlo, g_vlo);

    cudaFuncSetAttribute(mma_gemm, cudaFuncAttributeMaxDynamicSharedMemorySize, GEMM_SMEM);
    cudaFuncSetAttribute(flash_attn, cudaFuncAttributeMaxDynamicSharedMemorySize, FA_SMEM);

    const int nx4 = MTOT * D_ / 4;
    const int nw4 = D_ * D_ / 4;
    dim3 gx(B_, KE_, 16);
    dim3 gt(D_ / 128, (MTOT + 127) / 128);
    dim3 gl(B_, D_ / 64);

    split_bf16<<<(nx4 + 255) / 256, 256>>>((const float4*)hs, (uint2*)xhi, (uint2*)xlo, nx4);

    // Q
    xa_kernel<<<gx, 256>>>(hs, Aq, idx, xa);
    split_bf16<<<(nw4 + 255) / 256, 256>>>((const float4*)wq, (uint2*)whi, (uint2*)wlo, nw4);
    mma_gemm<<<gt, 256, GEMM_SMEM>>>(xhi, xlo, whi, wlo, bq, tmp, SCALE_Q);
    lora_split<<<gl, 256>>>(Bq, idx, gates, xa, tmp, qhi, qlo, SCALE_Q);
    // K
    xa_kernel<<<gx, 256>>>(hs, Ak, idx, xa);
    split_bf16<<<(nw4 + 255) / 256, 256>>>((const float4*)wk, (uint2*)whi, (uint2*)wlo, nw4);
    mma_gemm<<<gt, 256, GEMM_SMEM>>>(xhi, xlo, whi, wlo, bk, tmp, 1.f);
    lora_split<<<gl, 256>>>(Bk, idx, gates, xa, tmp, khi, klo, 1.f);
    // V
    xa_kernel<<<gx, 256>>>(hs, Av, idx, xa);
    split_bf16<<<(nw4 + 255) / 256, 256>>>((const float4*)wv, (uint2*)whi, (uint2*)wlo, nw4);
    mma_gemm<<<gt, 256, GEMM_SMEM>>>(xhi, xlo, whi, wlo, bv, tmp, 1.f);
    lora_split<<<gl, 256>>>(Bv, idx, gates, xa, tmp, vhi, vlo, 1.f);

    // fused attention
    flash_attn<<<dim3(B_ * H_, 3), 256, FA_SMEM>>>(qhi, qlo, khi, klo, vhi, vlo, x2);

    // O
    xa_kernel<<<gx, 256>>>(x2, Ao, idx, xa);
    split_bf16<<<(nx4 + 255) / 256, 256>>>((const float4*)x2, (uint2*)xhi, (uint2*)xlo, nx4);
    split_bf16<<<(nw4 + 255) / 256, 256>>>((const float4*)wo, (uint2*)whi, (uint2*)wlo, nw4);
    mma_gemm<<<gt, 256, GEMM_SMEM>>>(xhi, xlo, whi, wlo, bo, out, 1.f);
    lora_add<<<gl, 256>>>(Bo, idx, gates, xa, out, 1.f);
}

// round 7
// speedup vs baseline: 3.5509x; 1.0060x over previous
#include <cuda_runtime.h>
#include <cuda_bf16.h>
#include <cstdint>

#define B_ 32
#define S_ 257
#define D_ 1024
#define H_ 16
#define HD_ 64
#define E_ 8
#define R_ 16
#define KE_ 2
#define MTOT (B_*S_)
#define SCALE_Q 0.125f

// ---------------- scratch (device globals: allocation-free) ----------------
__device__ float g_tmp[(size_t)MTOT * D_];
__device__ float g_x2 [(size_t)MTOT * D_];
__device__ float g_xa [(size_t)B_ * KE_ * S_ * R_];
__device__ __nv_bfloat16 g_xhi[(size_t)MTOT * D_];
__device__ __nv_bfloat16 g_xlo[(size_t)MTOT * D_];
__device__ __nv_bfloat16 g_whi[(size_t)D_ * D_];
__device__ __nv_bfloat16 g_wlo[(size_t)D_ * D_];
__device__ __nv_bfloat16 g_qhi[(size_t)MTOT * D_];
__device__ __nv_bfloat16 g_qlo[(size_t)MTOT * D_];
__device__ __nv_bfloat16 g_khi[(size_t)MTOT * D_];
__device__ __nv_bfloat16 g_klo[(size_t)MTOT * D_];
__device__ __nv_bfloat16 g_vhi[(size_t)MTOT * D_];
__device__ __nv_bfloat16 g_vlo[(size_t)MTOT * D_];

// ========================= helpers (baseline PTX only) ======================
__device__ __forceinline__ uint32_t smem_u32(const void* p) {
    uint32_t a;
    asm("{ .reg .u64 t; cvta.to.shared.u64 t, %1; cvt.u32.u64 %0, t; }"
        : "=r"(a) : "l"(p));
    return a;
}

#define LDSM4(r0, r1, r2, r3, addr) \
    asm volatile("ldmatrix.sync.aligned.m8n8.x4.shared.b16 {%0,%1,%2,%3}, [%4];" \
        : "=r"(r0), "=r"(r1), "=r"(r2), "=r"(r3) : "r"(addr))

#define LDSM4T(r0, r1, r2, r3, addr) \
    asm volatile("ldmatrix.sync.aligned.m8n8.x4.trans.shared.b16 {%0,%1,%2,%3}, [%4];" \
        : "=r"(r0), "=r"(r1), "=r"(r2), "=r"(r3) : "r"(addr))

#define MMA16816(d, a, b0, b1) \
    asm volatile("mma.sync.aligned.m16n8k16.row.col.f32.bf16.bf16.f32 " \
        "{%0,%1,%2,%3}, {%4,%5,%6,%7}, {%8,%9}, {%0,%1,%2,%3};" \
        : "+f"((d)[0]), "+f"((d)[1]), "+f"((d)[2]), "+f"((d)[3]) \
        : "r"((a)[0]), "r"((a)[1]), "r"((a)[2]), "r"((a)[3]), "r"(b0), "r"(b1))

#define CP_ASYNC16(dst, src, sz) \
    asm volatile("cp.async.cg.shared.global [%0], [%1], 16, %2;" \
        :: "r"(dst), "l"(src), "r"(sz))
#define CP_COMMIT()  asm volatile("cp.async.commit_group;" ::: "memory")
#define CP_WAIT1()   asm volatile("cp.async.wait_group 1;" ::: "memory")
#define CP_WAIT0()   asm volatile("cp.async.wait_group 0;" ::: "memory")

// fast exp on FMA pipe: clamped; rel err ~2e-6
__device__ __forceinline__ float fexp(float x) {
    x = fmaxf(x, -80.f);
    float t = x * 1.4426950408889634f;
    float z = t + 12582912.f;
    int   k = __float_as_int(z) - 0x4B400000;
    float f = t - (z - 12582912.f);
    float p = 1.3333558146428443e-3f;
    p = fmaf(p, f, 9.6181291076284772e-3f);
    p = fmaf(p, f, 5.5504108664821580e-2f);
    p = fmaf(p, f, 2.4022650695910071e-1f);
    p = fmaf(p, f, 6.9314718055994531e-1f);
    p = fmaf(p, f, 1.0f);
    return __int_as_float(__float_as_int(p) + (k << 23));
}

// ============================================================================
// split fp32 -> (bf16 hi, bf16 lo)
// ============================================================================
__global__ __launch_bounds__(256) void split_bf16(
    const float4* __restrict__ x, uint2* __restrict__ hi, uint2* __restrict__ lo, int n4)
{
    int i = blockIdx.x * 256 + threadIdx.x;
    if (i >= n4) return;
    float4 v = x[i];
    __nv_bfloat162 h01 = __floats2bfloat162_rn(v.x, v.y);
    __nv_bfloat162 h23 = __floats2bfloat162_rn(v.z, v.w);
    float lx = v.x - __bfloat162float(h01.x);
    float ly = v.y - __bfloat162float(h01.y);
    float lz = v.z - __bfloat162float(h23.x);
    float lw = v.w - __bfloat162float(h23.y);
    __nv_bfloat162 l01 = __floats2bfloat162_rn(lx, ly);
    __nv_bfloat162 l23 = __floats2bfloat162_rn(lz, lw);
    uint2 hv, lv;
    hv.x = *(uint32_t*)&h01; hv.y = *(uint32_t*)&h23;
    lv.x = *(uint32_t*)&l01; lv.y = *(uint32_t*)&l23;
    hi[i] = hv; lo[i] = lv;
}

// ============================================================================
// HMMA GEMM: Y = (Xf32 @ Wf32^T + bias) * scale   via bf16x3 split
// Term-major MMA ordering: dependent HMMAs separated by 15 independents.
// ============================================================================
#define APITCH 80
#define TILEB (128 * APITCH)
#define STAGEB (4 * TILEB)
#define GEMM_SMEM (2 * STAGEB)

__device__ __forceinline__ void stage_load(
    uint32_t sb, int buf, int c, int tm, int tn, int tid,
    const __nv_bfloat16* __restrict__ Xhi, const __nv_bfloat16* __restrict__ Xlo,
    const __nv_bfloat16* __restrict__ Whi, const __nv_bfloat16* __restrict__ Wlo)
{
    uint32_t st = sb + buf * STAGEB;
    #pragma unroll
    for (int j = 0; j < 8; ++j) {
        int g = tid + j * 256;
        int tile = g >> 9, i = g & 511, row = i >> 2, seg = i & 3;
        const __nv_bfloat16* base = (tile == 0) ? Xhi : (tile == 1) ? Xlo
                                   : (tile == 2) ? Whi : Wlo;
        int grow = ((tile < 2) ? tm : tn) + row;
        const void* src = base + (size_t)grow * D_ + c * 32 + seg * 8;
        uint32_t dst = st + tile * TILEB + row * APITCH + seg * 16;
        int sz = (tile >= 2 || grow < MTOT) ? 16 : 0;
        CP_ASYNC16(dst, src, sz);
    }
}

__global__ __launch_bounds__(256) void mma_gemm(
    const __nv_bfloat16* __restrict__ Xhi, const __nv_bfloat16* __restrict__ Xlo,
    const __nv_bfloat16* __restrict__ Whi, const __nv_bfloat16* __restrict__ Wlo,
    const float* __restrict__ bias, float* __restrict__ Y, float scale)
{
    extern __shared__ char smem[];
    const uint32_t sb = smem_u32(smem);
    const int tid = threadIdx.x;
    const int wid = tid >> 5, lane = tid & 31;
    const int tm = blockIdx.y << 7, tn = blockIdx.x << 7;
    const int wm = (wid & 1) * 64, wn = (wid >> 1) * 32;

    const int lrow = lane & 15;
    const int lk   = lane >> 4;
    const int brow = ((lane >> 4) << 3) + (lane & 7);
    const int bk   = (lane >> 3) & 1;

    float acc[4][4][4] = {};

    stage_load(sb, 0, 0, tm, tn, tid, Xhi, Xlo, Whi, Wlo);
    CP_COMMIT();

    for (int c = 0; c < 32; ++c) {
        const int buf = c & 1;
        if (c + 1 < 32) {
            stage_load(sb, buf ^ 1, c + 1, tm, tn, tid, Xhi, Xlo, Whi, Wlo);
            CP_COMMIT();
            CP_WAIT1();
        } else {
            CP_WAIT0();
        }
        __syncthreads();

        const uint32_t Ah = sb + buf * STAGEB;
        const uint32_t Al = Ah + TILEB;
        const uint32_t Bh = Ah + 2 * TILEB;
        const uint32_t Bl = Ah + 3 * TILEB;

        #pragma unroll
        for (int kk2 = 0; kk2 < 2; ++kk2) {
            const int kkb = kk2 * 32;
            uint32_t ah[4][4], al[4][4], bh[2][4], bl[2][4];
            const uint32_t aoff = (uint32_t)(wm + lrow) * APITCH + kkb + lk * 16;
            const uint32_t boff = (uint32_t)(wn + brow) * APITCH + kkb + bk * 16;
            #pragma unroll
            for (int mt = 0; mt < 4; ++mt) {
                LDSM4(ah[mt][0], ah[mt][1], ah[mt][2], ah[mt][3],
                      Ah + aoff + mt * (16 * APITCH));
                LDSM4(al[mt][0], al[mt][1], al[mt][2], al[mt][3],
                      Al + aoff + mt * (16 * APITCH));
            }
            #pragma unroll
            for (int p = 0; p < 2; ++p) {
                LDSM4(bh[p][0], bh[p][1], bh[p][2], bh[p][3],
                      Bh + boff + p * (16 * APITCH));
                LDSM4(bl[p][0], bl[p][1], bl[p][2], bl[p][3],
                      Bl + boff + p * (16 * APITCH));
            }
            // term-major: all hi*hi, then all hi*lo, then all lo*hi
            #pragma unroll
            for (int mt = 0; mt < 4; ++mt)
                #pragma unroll
                for (int nt = 0; nt < 4; ++nt) {
                    const int p = nt >> 1, h = (nt & 1) * 2;
                    MMA16816(acc[mt][nt], ah[mt], bh[p][h], bh[p][h + 1]);
                }
            #pragma unroll
            for (int mt = 0; mt < 4; ++mt)
                #pragma unroll
                for (int nt = 0; nt < 4; ++nt) {
                    const int p = nt >> 1, h = (nt & 1) * 2;
                    MMA16816(acc[mt][nt], ah[mt], bl[p][h], bl[p][h + 1]);
                }
            #pragma unroll
            for (int mt = 0; mt < 4; ++mt)
                #pragma unroll
                for (int nt = 0; nt < 4; ++nt) {
                    const int p = nt >> 1, h = (nt & 1) * 2;
                    MMA16816(acc[mt][nt], al[mt], bh[p][h], bh[p][h + 1]);
                }
        }
        __syncthreads();
    }

    const int erow = lane >> 2, ecol = (lane & 3) * 2;
    #pragma unroll
    for (int mt = 0; mt < 4; ++mt) {
        #pragma unroll
        for (int nt = 0; nt < 4; ++nt) {
            int m0 = tm + wm + mt * 16 + erow;
            int n0 = tn + wn + nt * 8 + ecol;
            float bx = bias[n0], by = bias[n0 + 1];
            if (m0 < MTOT) {
                float2 o;
                o.x = (acc[mt][nt][0] + bx) * scale;
                o.y = (acc[mt][nt][1] + by) * scale;
                *(float2*)(Y + (size_t)m0 * D_ + n0) = o;
            }
            if (m0 + 8 < MTOT) {
                float2 o;
                o.x = (acc[mt][nt][2] + bx) * scale;
                o.y = (acc[mt][nt][3] + by) * scale;
                *(float2*)(Y + (size_t)(m0 + 8) * D_ + n0) = o;
            }
        }
    }
}

// ============================================================================
// Fused flash attention (rows 0..255): grid (512, 2).
// Term-major MMA ordering throughout.
// ============================================================================
#define FPITCH 144
#define KVROWB (64 * FPITCH)
#define KVSTG  (4 * KVROWB)
#define FA_SMEM (2 * KVSTG)

__device__ __forceinline__ void load_kv(
    uint32_t st, int t0, size_t kvbase, int tid,
    const __nv_bfloat16* __restrict__ khi, const __nv_bfloat16* __restrict__ klo,
    const __nv_bfloat16* __restrict__ vhi, const __nv_bfloat16* __restrict__ vlo)
{
    #pragma unroll
    for (int j = 0; j < 8; ++j) {
        int g = tid + j * 256;
        int tens = g >> 9, i = g & 511, row = i >> 3, seg = i & 7;
        const __nv_bfloat16* bp = (tens == 0) ? khi : (tens == 1) ? klo
                                 : (tens == 2) ? vhi : vlo;
        const void* src = bp + kvbase + (size_t)(t0 + row) * D_ + seg * 8;
        uint32_t dst = st + tens * KVROWB + row * FPITCH + seg * 16;
        CP_ASYNC16(dst, src, (t0 + row) < S_ ? 16 : 0);
    }
}

__global__ __launch_bounds__(256, 1) void flash_attn(
    const __nv_bfloat16* __restrict__ qhi, const __nv_bfloat16* __restrict__ qlo,
    const __nv_bfloat16* __restrict__ khi, const __nv_bfloat16* __restrict__ klo,
    const __nv_bfloat16* __restrict__ vhi, const __nv_bfloat16* __restrict__ vlo,
    float* __restrict__ Xo)
{
    extern __shared__ char smem[];
    const uint32_t sb = smem_u32(smem);
    const int tid = threadIdx.x, wid = tid >> 5, lane = tid & 31;
    const int bh = blockIdx.x, b = bh >> 4, h = bh & 15;
    const int m0 = blockIdx.y * 128;
    const size_t kvbase = (size_t)b * S_ * D_ + h * HD_;

    #pragma unroll
    for (int j = 0; j < 8; ++j) {
        int g = tid + j * 256;
        int half = g >> 10, i = g & 1023, row = i >> 3, seg = i & 7;
        const __nv_bfloat16* src = (half ? qlo : qhi) + kvbase
                                 + (size_t)(m0 + row) * D_ + seg * 8;
        uint32_t dst = sb + half * KVSTG + row * FPITCH + seg * 16;
        CP_ASYNC16(dst, src, (m0 + row) < S_ ? 16 : 0);
    }
    CP_COMMIT(); CP_WAIT0();
    __syncthreads();

    uint32_t qh[4][4], ql[4][4];
    {
        const uint32_t base = sb + (uint32_t)(wid * 16 + (lane & 15)) * FPITCH
                            + (lane >> 4) * 16;
        #pragma unroll
        for (int kk = 0; kk < 4; ++kk) {
            LDSM4(qh[kk][0], qh[kk][1], qh[kk][2], qh[kk][3], base + kk * 32);
            LDSM4(ql[kk][0], ql[kk][1], ql[kk][2], ql[kk][3], base + KVSTG + kk * 32);
        }
    }
    __syncthreads();

    float acc_o[8][4] = {};
    float mrow[2] = {-1e30f, -1e30f}, lrow[2] = {0.f, 0.f};
    const int brow = ((lane >> 4) << 3) + (lane & 7);
    const int bk   = (lane >> 3) & 1;
    const int quad = lane & 3;

    load_kv(sb, 0, kvbase, tid, khi, klo, vhi, vlo);
    CP_COMMIT();

    #pragma unroll 1
    for (int kv = 0; kv < 5; ++kv) {
        CP_WAIT0();
        __syncthreads();
        const uint32_t Ks = sb + (kv & 1) * KVSTG;
        const uint32_t Vs = Ks + 2 * KVROWB;
        if (kv < 4) {
            load_kv(sb + ((kv + 1) & 1) * KVSTG, (kv + 1) * 64, kvbase, tid,
                    khi, klo, vhi, vlo);
            CP_COMMIT();
        }

        // ---- scores S = q k^T (bf16x3, term-major)
        float s[8][4] = {};
        #pragma unroll
        for (int kk = 0; kk < 4; ++kk) {
            uint32_t kh[4][4], kl[4][4];
            #pragma unroll
            for (int p = 0; p < 4; ++p) {
                uint32_t ko = Ks + (uint32_t)(p * 16 + brow) * FPITCH + kk * 32 + bk * 16;
                LDSM4(kh[p][0], kh[p][1], kh[p][2], kh[p][3], ko);
                LDSM4(kl[p][0], kl[p][1], kl[p][2], kl[p][3], ko + KVROWB);
            }
            #pragma unroll
            for (int p = 0; p < 4; ++p) {
                MMA16816(s[2*p],   qh[kk], kh[p][0], kh[p][1]);
                MMA16816(s[2*p+1], qh[kk], kh[p][2], kh[p][3]);
            }
            #pragma unroll
            for (int p = 0; p < 4; ++p) {
                MMA16816(s[2*p],   qh[kk], kl[p][0], kl[p][1]);
                MMA16816(s[2*p+1], qh[kk], kl[p][2], kl[p][3]);
            }
            #pragma unroll
            for (int p = 0; p < 4; ++p) {
                MMA16816(s[2*p],   ql[kk], kh[p][0], kh[p][1]);
                MMA16816(s[2*p+1], ql[kk], kh[p][2], kh[p][3]);
            }
        }

        if (kv == 4) {
            #pragma unroll
            for (int nt = 0; nt < 8; ++nt)
                #pragma unroll
                for (int rg = 0; rg < 4; ++rg) {
                    int col = 256 + nt * 8 + quad * 2 + (rg & 1);
                    if (col >= S_) s[nt][rg] = -1e30f;
                }
        }

        // ---- online softmax
        #pragma unroll
        for (int rr = 0; rr < 2; ++rr) {
            float mx = -1e30f;
            #pragma unroll
            for (int nt = 0; nt < 8; ++nt)
                mx = fmaxf(mx, fmaxf(s[nt][2*rr], s[nt][2*rr+1]));
            mx = fmaxf(mx, __shfl_xor_sync(0xffffffffu, mx, 1));
            mx = fmaxf(mx, __shfl_xor_sync(0xffffffffu, mx, 2));
            float mnew = fmaxf(mrow[rr], mx);
            float alpha = fexp(mrow[rr] - mnew);
            mrow[rr] = mnew;
            float sum = 0.f;
            #pragma unroll
            for (int nt = 0; nt < 8; ++nt) {
                float p0 = fexp(s[nt][2*rr]   - mnew);
                float p1 = fexp(s[nt][2*rr+1] - mnew);
                s[nt][2*rr] = p0; s[nt][2*rr+1] = p1;
                sum += p0 + p1;
            }
            sum += __shfl_xor_sync(0xffffffffu, sum, 1);
            sum += __shfl_xor_sync(0xffffffffu, sum, 2);
            lrow[rr] = lrow[rr] * alpha + sum;
            #pragma unroll
            for (int nt = 0; nt < 8; ++nt) {
                acc_o[nt][2*rr]   *= alpha;
                acc_o[nt][2*rr+1] *= alpha;
            }
        }

        // ---- out += P V (term-major)
        #pragma unroll
        for (int kk = 0; kk < 4; ++kk) {
            uint32_t ph[4], pl[4];
            #pragma unroll
            for (int rg = 0; rg < 4; ++rg) {
                int nt = 2 * kk + (rg >> 1);
                float p0 = s[nt][(rg & 1) * 2];
                float p1 = s[nt][(rg & 1) * 2 + 1];
                __nv_bfloat162 hb = __floats2bfloat162_rn(p0, p1);
                float l0 = p0 - __bfloat162float(hb.x);
                float l1 = p1 - __bfloat162float(hb.y);
                __nv_bfloat162 lb = __floats2bfloat162_rn(l0, l1);
                ph[rg] = *(uint32_t*)&hb;
                pl[rg] = *(uint32_t*)&lb;
            }
            uint32_t vh[4][4], vl[4][4];
            #pragma unroll
            for (int p = 0; p < 4; ++p) {
                uint32_t vo = Vs + (uint32_t)(kk * 16 + (lane & 15)) * FPITCH
                            + p * 32 + (lane >> 4) * 16;
                LDSM4T(vh[p][0], vh[p][1], vh[p][2], vh[p][3], vo);
                LDSM4T(vl[p][0], vl[p][1], vl[p][2], vl[p][3], vo + KVROWB);
            }
            #pragma unroll
            for (int p = 0; p < 4; ++p) {
                MMA16816(acc_o[2*p],   ph, vh[p][0], vh[p][1]);
                MMA16816(acc_o[2*p+1], ph, vh[p][2], vh[p][3]);
            }
            #pragma unroll
            for (int p = 0; p < 4; ++p) {
                MMA16816(acc_o[2*p],   ph, vl[p][0], vl[p][1]);
                MMA16816(acc_o[2*p+1], ph, vl[p][2], vl[p][3]);
            }
            #pragma unroll
            for (int p = 0; p < 4; ++p) {
                MMA16816(acc_o[2*p],   pl, vh[p][0], vh[p][1]);
                MMA16816(acc_o[2*p+1], pl, vh[p][2], vh[p][3]);
            }
        }
    }

    {
        const int r = lane >> 2, q2 = quad * 2;
        #pragma unroll
        for (int rr = 0; rr < 2; ++rr) {
            int m = m0 + wid * 16 + r + rr * 8;
            if (m < S_) {
                float inv = 1.f / lrow[rr];
                float* op = Xo + ((size_t)b * S_ + m) * D_ + h * HD_ + q2;
                #pragma unroll
                for (int nt = 0; nt < 8; ++nt) {
                    float2 o;
                    o.x = acc_o[nt][2*rr]   * inv;
                    o.y = acc_o[nt][2*rr+1] * inv;
                    *(float2*)(op + nt * 8) = o;
                }
            }
        }
    }
}

// ============================================================================
// attn_tail: attention for the single query row s = 256, one block per (b,h).
// ============================================================================
#define TAIL_SMEM ((257 * 65 + 64 + 257 + 256) * 4)
__global__ __launch_bounds__(256) void attn_tail(
    const __nv_bfloat16* __restrict__ qhi, const __nv_bfloat16* __restrict__ qlo,
    const __nv_bfloat16* __restrict__ khi, const __nv_bfloat16* __restrict__ klo,
    const __nv_bfloat16* __restrict__ vhi, const __nv_bfloat16* __restrict__ vlo,
    float* __restrict__ Xo)
{
    extern __shared__ float fs[];
    float* ks  = fs;                    // [257][65]
    float* q   = ks + 257 * 65;        // [64]
    float* p   = q + 64;               // [257]
    float* red = p + 257;              // [256]
    const int t = threadIdx.x;
    const int bh = blockIdx.x, b = bh >> 4, h = bh & 15;
    const size_t base = (size_t)b * S_ * D_ + h * HD_;

    if (t < 64) {
        size_t o = base + (size_t)256 * D_ + t;
        q[t] = __bfloat162float(qhi[o]) + __bfloat162float(qlo[o]);
    }
    for (int i = t; i < 257 * 64; i += 256) {
        int row = i >> 6, d = i & 63;
        size_t o = base + (size_t)row * D_ + d;
        ks[row * 65 + d] = __bfloat162float(khi[o]) + __bfloat162float(klo[o]);
    }
    __syncthreads();

    float v0 = 0.f, v1 = -1e30f;
    {
        const float* kr = ks + t * 65;
        #pragma unroll 8
        for (int d = 0; d < 64; ++d) v0 = fmaf(q[d], kr[d], v0);
    }
    if (t == 0) {
        v1 = 0.f;
        const float* kr = ks + 256 * 65;
        #pragma unroll 8
        for (int d = 0; d < 64; ++d) v1 = fmaf(q[d], kr[d], v1);
    }

    red[t] = fmaxf(v0, v1);
    __syncthreads();
    #pragma unroll
    for (int o = 128; o; o >>= 1) {
        if (t < o) red[t] = fmaxf(red[t], red[t + o]);
        __syncthreads();
    }
    float rmax = red[0];
    __syncthreads();
    float e0 = fexp(v0 - rmax);
    float e1 = (t == 0) ? fexp(v1 - rmax) : 0.f;
    red[t] = e0 + e1;
    __syncthreads();
    #pragma unroll
    for (int o = 128; o; o >>= 1) {
        if (t < o) red[t] += red[t + o];
        __syncthreads();
    }
    float inv = 1.f / red[0];
    p[t] = e0 * inv;
    if (t == 0) p[256] = e1 * inv;
    __syncthreads();

    if (t < 64) {
        float o = 0.f;
        for (int tt = 0; tt < S_; ++tt) {
            size_t off = base + (size_t)tt * D_ + t;
            o = fmaf(p[tt], __bfloat162float(vhi[off]) + __bfloat162float(vlo[off]), o);
        }
        Xo[((size_t)b * S_ + 256) * D_ + h * HD_ + t] = o;
    }
}

// ============================================================================
// xa[b,slot,s,r] = sum_d X[b,s,d] * A[idx[b,slot], r, d]
// ============================================================================
__global__ __launch_bounds__(256) void xa_kernel(
    const float* __restrict__ X, const float* __restrict__ A,
    const int* __restrict__ idx, float* __restrict__ xa)
{
    int b = blockIdx.x, slot = blockIdx.y;
    int rh = blockIdx.z >> 3, sc = blockIdx.z & 7;
    int sbase = sc * 33;
    int smax = min(S_, sbase + 33);
    int e = idx[b * KE_ + slot];
    __shared__ float As[8][D_];
    const float* Ap = A + ((size_t)e * R_ + rh * 8) * D_;
    for (int i = threadIdx.x; i < 8 * D_ / 4; i += 256)
        ((float4*)As)[i] = ((const float4*)Ap)[i];
    __syncthreads();

    int w = threadIdx.x >> 5, lane = threadIdx.x & 31;
    for (int s4 = sbase + w * 4; s4 < smax; s4 += 32) {
        float sum[8][4];
        #pragma unroll
        for (int r = 0; r < 8; r++)
            #pragma unroll
            for (int si = 0; si < 4; si++) sum[r][si] = 0.f;

        #pragma unroll 1
        for (int c = 0; c < 8; c++) {
            float4 xv[4];
            #pragma unroll
            for (int si = 0; si < 4; si++) {
                int s = s4 + si;
                xv[si] = (s < S_)
                    ? *(const float4*)(X + ((size_t)b * S_ + s) * D_ + c * 128 + lane * 4)
                    : make_float4(0.f, 0.f, 0.f, 0.f);
            }
            #pragma unroll
            for (int r = 0; r < 8; r++) {
                float4 av = *(const float4*)&As[r][c * 128 + lane * 4];
                #pragma unroll
                for (int si = 0; si < 4; si++)
                    sum[r][si] = fmaf(xv[si].x, av.x,
                                 fmaf(xv[si].y, av.y,
                                 fmaf(xv[si].z, av.z,
                                 fmaf(xv[si].w, av.w, sum[r][si]))));
            }
        }
        #pragma unroll
        for (int r = 0; r < 8; r++)
            #pragma unroll
            for (int si = 0; si < 4; si++) {
                float v = sum[r][si];
                #pragma unroll
                for (int o = 16; o; o >>= 1) v += __shfl_xor_sync(0xffffffffu, v, o);
                int s = s4 + si;
                if (lane == 0 && s < S_)
                    xa[(((size_t)b * KE_ + slot) * S_ + s) * R_ + rh * 8 + r] = v;
            }
    }
}

// ============================================================================
// lora_add: Y += gated LoRA (fp32, for the O projection)
// ============================================================================
__global__ __launch_bounds__(256) void lora_add(
    const float* __restrict__ Bm, const int* __restrict__ idx,
    const float* __restrict__ gates, const float* __restrict__ xa,
    float* __restrict__ Y, float scale)
{
    int b = blockIdx.x;
    int cn = blockIdx.y << 6;
    int t = threadIdx.x;
    __shared__ float Bs[2][64][17];
    __shared__ float xs[2][64][17];
    int e0 = idx[b * KE_], e1 = idx[b * KE_ + 1];
    float g0 = gates[b * KE_] * scale, g1 = gates[b * KE_ + 1] * scale;

    for (int i = t; i < 2048; i += 256) {
        int slot = i >> 10, rem = i & 1023, c = rem >> 4, r = rem & 15;
        Bs[slot][c][r] = Bm[((size_t)(slot ? e1 : e0) * D_ + cn + c) * R_ + r];
    }

    int c = t & 63, sq = t >> 6;
    for (int s0 = 0; s0 < S_; s0 += 64) {
        __syncthreads();
        for (int i = t; i < 2048; i += 256) {
            int slot = i >> 10, rem = i & 1023, si = rem >> 4, r = rem & 15;
            int s = s0 + si;
            float v = (s < S_) ? xa[(((size_t)b * KE_ + slot) * S_ + s) * R_ + r] : 0.f;
            xs[slot][si][r] = v * (slot ? g1 : g0);
        }
        __syncthreads();
        for (int si = sq; si < 64; si += 4) {
            int s = s0 + si;
            if (s >= S_) break;
            float sum = 0.f;
            #pragma unroll
            for (int r = 0; r < 16; r++) {
                sum = fmaf(xs[0][si][r], Bs[0][c][r], sum);
                sum = fmaf(xs[1][si][r], Bs[1][c][r], sum);
            }
            Y[((size_t)b * S_ + s) * D_ + cn + c] += sum;
        }
    }
}

// ============================================================================
// lora_split: out = Yin + gated LoRA, written as bf16 hi/lo split (q/k/v)
// ============================================================================
__global__ __launch_bounds__(256) void lora_split(
    const float* __restrict__ Bm, const int* __restrict__ idx,
    const float* __restrict__ gates, const float* __restrict__ xa,
    const float* __restrict__ Yin,
    __nv_bfloat16* __restrict__ Yhi, __nv_bfloat16* __restrict__ Ylo, float scale)
{
    int b = blockIdx.x;
    int cn = blockIdx.y << 6;
    int t = threadIdx.x;
    __shared__ float Bs[2][64][17];
    __shared__ float xs[2][64][17];
    int e0 = idx[b * KE_], e1 = idx[b * KE_ + 1];
    float g0 = gates[b * KE_] * scale, g1 = gates[b * KE_ + 1] * scale;

    for (int i = t; i < 2048; i += 256) {
        int slot = i >> 10, rem = i & 1023, c = rem >> 4, r = rem & 15;
        Bs[slot][c][r] = Bm[((size_t)(slot ? e1 : e0) * D_ + cn + c) * R_ + r];
    }

    int c = t & 63, sq = t >> 6;
    for (int s0 = 0; s0 < S_; s0 += 64) {
        __syncthreads();
        for (int i = t; i < 2048; i += 256) {
            int slot = i >> 10, rem = i & 1023, si = rem >> 4, r = rem & 15;
            int s = s0 + si;
            float v = (s < S_) ? xa[(((size_t)b * KE_ + slot) * S_ + s) * R_ + r] : 0.f;
            xs[slot][si][r] = v * (slot ? g1 : g0);
        }
        __syncthreads();
        for (int si = sq; si < 64; si += 4) {
            int s = s0 + si;
            if (s >= S_) break;
            float sum = 0.f;
            #pragma unroll
            for (int r = 0; r < 16; r++) {
                sum = fmaf(xs[0][si][r], Bs[0][c][r], sum);
                sum = fmaf(xs[1][si][r], Bs[1][c][r], sum);
            }
            size_t off = ((size_t)b * S_ + s) * D_ + cn + c;
            float v = Yin[off] + sum;
            __nv_bfloat16 hb = __float2bfloat16(v);
            Yhi[off] = hb;
            Ylo[off] = __float2bfloat16(v - __bfloat162float(hb));
        }
    }
}

// ---------------- host launcher --------------------------------------------
extern "C" void kernel_launch(void* const* d_in, const int* in_sizes, int n_in,
                              void* d_out, int out_size)
{
    const float* hs    = (const float*)d_in[0];
    const int*   idx   = (const int*)  d_in[1];
    const float* gates = (const float*)d_in[2];
    const float* wq = (const float*)d_in[3];  const float* Aq = (const float*)d_in[4];
    const float* Bq = (const float*)d_in[5];  const float* bq = (const float*)d_in[6];
    const float* wk = (const float*)d_in[7];  const float* Ak = (const float*)d_in[8];
    const float* Bk = (const float*)d_in[9];  const float* bk = (const float*)d_in[10];
    const float* wv = (const float*)d_in[11]; const float* Av = (const float*)d_in[12];
    const float* Bv = (const float*)d_in[13]; const float* bv = (const float*)d_in[14];
    const float* wo = (const float*)d_in[15]; const float* Ao = (const float*)d_in[16];
    const float* Bo = (const float*)d_in[17]; const float* bo = (const float*)d_in[18];
    float* out = (float*)d_out;

    float *tmp, *x2, *xa;
    __nv_bfloat16 *xhi, *xlo, *whi, *wlo, *qhi, *qlo, *khi, *klo, *vhi, *vlo;
    cudaGetSymbolAddress((void**)&tmp, g_tmp);
    cudaGetSymbolAddress((void**)&x2,  g_x2);
    cudaGetSymbolAddress((void**)&xa,  g_xa);
    cudaGetSymbolAddress((void**)&xhi, g_xhi);
    cudaGetSymbolAddress((void**)&xlo, g_xlo);
    cudaGetSymbolAddress((void**)&whi, g_whi);
    cudaGetSymbolAddress((void**)&wlo, g_wlo);
    cudaGetSymbolAddress((void**)&qhi, g_qhi);
    cudaGetSymbolAddress((void**)&qlo, g_qlo);
    cudaGetSymbolAddress((void**)&khi, g_khi);
    cudaGetSymbolAddress((void**)&klo, g_klo);
    cudaGetSymbolAddress((void**)&vhi, g_vhi);
    cudaGetSymbolAddress((void**)&vlo, g_vlo);

    cudaFuncSetAttribute(mma_gemm, cudaFuncAttributeMaxDynamicSharedMemorySize, GEMM_SMEM);
    cudaFuncSetAttribute(flash_attn, cudaFuncAttributeMaxDynamicSharedMemorySize, FA_SMEM);
    cudaFuncSetAttribute(attn_tail, cudaFuncAttributeMaxDynamicSharedMemorySize, TAIL_SMEM);

    const int nx4 = MTOT * D_ / 4;
    const int nw4 = D_ * D_ / 4;
    dim3 gx(B_, KE_, 16);
    dim3 gt(D_ / 128, (MTOT + 127) / 128);
    dim3 gl(B_, D_ / 64);

    split_bf16<<<(nx4 + 255) / 256, 256>>>((const float4*)hs, (uint2*)xhi, (uint2*)xlo, nx4);

    // Q
    xa_kernel<<<gx, 256>>>(hs, Aq, idx, xa);
    split_bf16<<<(nw4 + 255) / 256, 256>>>((const float4*)wq, (uint2*)whi, (uint2*)wlo, nw4);
    mma_gemm<<<gt, 256, GEMM_SMEM>>>(xhi, xlo, whi, wlo, bq, tmp, SCALE_Q);
    lora_split<<<gl, 256>>>(Bq, idx, gates, xa, tmp, qhi, qlo, SCALE_Q);
    // K
    xa_kernel<<<gx, 256>>>(hs, Ak, idx, xa);
    split_bf16<<<(nw4 + 255) / 256, 256>>>((const float4*)wk, (uint2*)whi, (uint2*)wlo, nw4);
    mma_gemm<<<gt, 256, GEMM_SMEM>>>(xhi, xlo, whi, wlo, bk, tmp, 1.f);
    lora_split<<<gl, 256>>>(Bk, idx, gates, xa, tmp, khi, klo, 1.f);
    // V
    xa_kernel<<<gx, 256>>>(hs, Av, idx, xa);
    split_bf16<<<(nw4 + 255) / 256, 256>>>((const float4*)wv, (uint2*)whi, (uint2*)wlo, nw4);
    mma_gemm<<<gt, 256, GEMM_SMEM>>>(xhi, xlo, whi, wlo, bv, tmp, 1.f);
    lora_split<<<gl, 256>>>(Bv, idx, gates, xa, tmp, vhi, vlo, 1.f);

    // fused attention (rows 0..255) + tail row 256
    flash_attn<<<dim3(B_ * H_, 2), 256, FA_SMEM>>>(qhi, qlo, khi, klo, vhi, vlo, x2);
    attn_tail<<<B_ * H_, 256, TAIL_SMEM>>>(qhi, qlo, khi, klo, vhi, vlo, x2);

    // O
    xa_kernel<<<gx, 256>>>(x2, Ao, idx, xa);
    split_bf16<<<(nx4 + 255) / 256, 256>>>((const float4*)x2, (uint2*)xhi, (uint2*)xlo, nx4);
    split_bf16<<<(nw4 + 255) / 256, 256>>>((const float4*)wo, (uint2*)whi, (uint2*)wlo, nw4);
    mma_gemm<<<gt, 256, GEMM_SMEM>>>(xhi, xlo, whi, wlo, bo, out, 1.f);
    lora_add<<<gl, 256>>>(Bo, idx, gates, xa, out, 1.f);
}

// round 8
// speedup vs baseline: 3.9931x; 1.1246x over previous
#include <cuda_runtime.h>
#include <cuda_bf16.h>
#include <cstdint>

#define B_ 32
#define S_ 257
#define D_ 1024
#define H_ 16
#define HD_ 64
#define E_ 8
#define R_ 16
#define KE_ 2
#define MTOT (B_*S_)
#define SCALE_Q 0.125f

// ---------------- scratch (device globals: allocation-free) ----------------
__device__ float g_tmp[(size_t)3 * MTOT * D_];
__device__ float g_x2 [(size_t)MTOT * D_];
__device__ float g_xa [(size_t)3 * B_ * KE_ * S_ * R_];
__device__ __nv_bfloat16 g_xhi[(size_t)MTOT * D_];
__device__ __nv_bfloat16 g_xlo[(size_t)MTOT * D_];
__device__ __nv_bfloat16 g_whi[(size_t)3 * D_ * D_];
__device__ __nv_bfloat16 g_wlo[(size_t)3 * D_ * D_];
__device__ __nv_bfloat16 g_qhi[(size_t)MTOT * D_];
__device__ __nv_bfloat16 g_qlo[(size_t)MTOT * D_];
__device__ __nv_bfloat16 g_khi[(size_t)MTOT * D_];
__device__ __nv_bfloat16 g_klo[(size_t)MTOT * D_];
__device__ __nv_bfloat16 g_vhi[(size_t)MTOT * D_];
__device__ __nv_bfloat16 g_vlo[(size_t)MTOT * D_];

// ========================= helpers (baseline PTX only) ======================
__device__ __forceinline__ uint32_t smem_u32(const void* p) {
    uint32_t a;
    asm("{ .reg .u64 t; cvta.to.shared.u64 t, %1; cvt.u32.u64 %0, t; }"
        : "=r"(a) : "l"(p));
    return a;
}

#define LDSM4(r0, r1, r2, r3, addr) \
    asm volatile("ldmatrix.sync.aligned.m8n8.x4.shared.b16 {%0,%1,%2,%3}, [%4];" \
        : "=r"(r0), "=r"(r1), "=r"(r2), "=r"(r3) : "r"(addr))

#define LDSM4T(r0, r1, r2, r3, addr) \
    asm volatile("ldmatrix.sync.aligned.m8n8.x4.trans.shared.b16 {%0,%1,%2,%3}, [%4];" \
        : "=r"(r0), "=r"(r1), "=r"(r2), "=r"(r3) : "r"(addr))

// NOTE: non-volatile — lets ptxas interleave/pipeline MMAs with LDSMs.
#define MMA16816(d, a, b0, b1) \
    asm("mma.sync.aligned.m16n8k16.row.col.f32.bf16.bf16.f32 " \
        "{%0,%1,%2,%3}, {%4,%5,%6,%7}, {%8,%9}, {%0,%1,%2,%3};" \
        : "+f"((d)[0]), "+f"((d)[1]), "+f"((d)[2]), "+f"((d)[3]) \
        : "r"((a)[0]), "r"((a)[1]), "r"((a)[2]), "r"((a)[3]), "r"(b0), "r"(b1))

#define CP_ASYNC16(dst, src, sz) \
    asm volatile("cp.async.cg.shared.global [%0], [%1], 16, %2;" \
        :: "r"(dst), "l"(src), "r"(sz))
#define CP_COMMIT()  asm volatile("cp.async.commit_group;" ::: "memory")
#define CP_WAIT1()   asm volatile("cp.async.wait_group 1;" ::: "memory")
#define CP_WAIT0()   asm volatile("cp.async.wait_group 0;" ::: "memory")

// fast exp on FMA pipe
__device__ __forceinline__ float fexp(float x) {
    x = fmaxf(x, -80.f);
    float t = x * 1.4426950408889634f;
    float z = t + 12582912.f;
    int   k = __float_as_int(z) - 0x4B400000;
    float f = t - (z - 12582912.f);
    float p = 1.3333558146428443e-3f;
    p = fmaf(p, f, 9.6181291076284772e-3f);
    p = fmaf(p, f, 5.5504108664821580e-2f);
    p = fmaf(p, f, 2.4022650695910071e-1f);
    p = fmaf(p, f, 6.9314718055994531e-1f);
    p = fmaf(p, f, 1.0f);
    return __int_as_float(__float_as_int(p) + (k << 23));
}

// ============================================================================
// split fp32 -> (bf16 hi, bf16 lo)
// ============================================================================
__device__ __forceinline__ void split_one(
    const float4* __restrict__ x, uint2* __restrict__ hi, uint2* __restrict__ lo, int i)
{
    float4 v = x[i];
    __nv_bfloat162 h01 = __floats2bfloat162_rn(v.x, v.y);
    __nv_bfloat162 h23 = __floats2bfloat162_rn(v.z, v.w);
    float lx = v.x - __bfloat162float(h01.x);
    float ly = v.y - __bfloat162float(h01.y);
    float lz = v.z - __bfloat162float(h23.x);
    float lw = v.w - __bfloat162float(h23.y);
    __nv_bfloat162 l01 = __floats2bfloat162_rn(lx, ly);
    __nv_bfloat162 l23 = __floats2bfloat162_rn(lz, lw);
    uint2 hv, lv;
    hv.x = *(uint32_t*)&h01; hv.y = *(uint32_t*)&h23;
    lv.x = *(uint32_t*)&l01; lv.y = *(uint32_t*)&l23;
    hi[i] = hv; lo[i] = lv;
}

__global__ __launch_bounds__(256) void split_bf16(
    const float4* __restrict__ x, uint2* __restrict__ hi, uint2* __restrict__ lo, int n4)
{
    int i = blockIdx.x * 256 + threadIdx.x;
    if (i < n4) split_one(x, hi, lo, i);
}

// 3-way W split: grid.y selects source, writes at offset y*D*D
__global__ __launch_bounds__(256) void split_w3(
    const float4* __restrict__ w0, const float4* __restrict__ w1,
    const float4* __restrict__ w2, uint2* __restrict__ hi, uint2* __restrict__ lo)
{
    const int n4 = D_ * D_ / 4;
    int i = blockIdx.x * 256 + threadIdx.x;
    if (i >= n4) return;
    int z = blockIdx.y;
    const float4* src = (z == 0) ? w0 : (z == 1) ? w1 : w2;
    split_one(src, hi + (size_t)z * n4, lo + (size_t)z * n4, i);
}

// ============================================================================
// HMMA GEMM: Y = (Xf32 @ Wf32^T + bias) * scale   via bf16x3 split
// grid.z selects projection (W offset, bias, scale, Y offset).
// ============================================================================
#define APITCH 80
#define TILEB (128 * APITCH)
#define STAGEB (4 * TILEB)
#define GEMM_SMEM (2 * STAGEB)

__device__ __forceinline__ void stage_load(
    uint32_t sb, int buf, int c, int tm, int tn, int tid,
    const __nv_bfloat16* __restrict__ Xhi, const __nv_bfloat16* __restrict__ Xlo,
    const __nv_bfloat16* __restrict__ Whi, const __nv_bfloat16* __restrict__ Wlo)
{
    uint32_t st = sb + buf * STAGEB;
    #pragma unroll
    for (int j = 0; j < 8; ++j) {
        int g = tid + j * 256;
        int tile = g >> 9, i = g & 511, row = i >> 2, seg = i & 3;
        const __nv_bfloat16* base = (tile == 0) ? Xhi : (tile == 1) ? Xlo
                                   : (tile == 2) ? Whi : Wlo;
        int grow = ((tile < 2) ? tm : tn) + row;
        const void* src = base + (size_t)grow * D_ + c * 32 + seg * 8;
        uint32_t dst = st + tile * TILEB + row * APITCH + seg * 16;
        int sz = (tile >= 2 || grow < MTOT) ? 16 : 0;
        CP_ASYNC16(dst, src, sz);
    }
}

__device__ __forceinline__ void gemm_body(
    const __nv_bfloat16* __restrict__ Xhi, const __nv_bfloat16* __restrict__ Xlo,
    const __nv_bfloat16* __restrict__ Whi, const __nv_bfloat16* __restrict__ Wlo,
    const float* __restrict__ bias, float* __restrict__ Y, float scale)
{
    extern __shared__ char smem[];
    const uint32_t sb = smem_u32(smem);
    const int tid = threadIdx.x;
    const int wid = tid >> 5, lane = tid & 31;
    const int tm = blockIdx.y << 7, tn = blockIdx.x << 7;
    const int wm = (wid & 1) * 64, wn = (wid >> 1) * 32;

    const int lrow = lane & 15;
    const int lk   = lane >> 4;
    const int brow = ((lane >> 4) << 3) + (lane & 7);
    const int bk   = (lane >> 3) & 1;

    float acc[4][4][4] = {};

    stage_load(sb, 0, 0, tm, tn, tid, Xhi, Xlo, Whi, Wlo);
    CP_COMMIT();

    for (int c = 0; c < 32; ++c) {
        const int buf = c & 1;
        if (c + 1 < 32) {
            stage_load(sb, buf ^ 1, c + 1, tm, tn, tid, Xhi, Xlo, Whi, Wlo);
            CP_COMMIT();
            CP_WAIT1();
        } else {
            CP_WAIT0();
        }
        __syncthreads();

        const uint32_t Ah = sb + buf * STAGEB;
        const uint32_t Al = Ah + TILEB;
        const uint32_t Bh = Ah + 2 * TILEB;
        const uint32_t Bl = Ah + 3 * TILEB;

        #pragma unroll
        for (int kk2 = 0; kk2 < 2; ++kk2) {
            const int kkb = kk2 * 32;
            uint32_t ah[4][4], al[4][4], bh[2][4], bl[2][4];
            const uint32_t aoff = (uint32_t)(wm + lrow) * APITCH + kkb + lk * 16;
            const uint32_t boff = (uint32_t)(wn + brow) * APITCH + kkb + bk * 16;
            #pragma unroll
            for (int mt = 0; mt < 4; ++mt) {
                LDSM4(ah[mt][0], ah[mt][1], ah[mt][2], ah[mt][3],
                      Ah + aoff + mt * (16 * APITCH));
                LDSM4(al[mt][0], al[mt][1], al[mt][2], al[mt][3],
                      Al + aoff + mt * (16 * APITCH));
            }
            #pragma unroll
            for (int p = 0; p < 2; ++p) {
                LDSM4(bh[p][0], bh[p][1], bh[p][2], bh[p][3],
                      Bh + boff + p * (16 * APITCH));
                LDSM4(bl[p][0], bl[p][1], bl[p][2], bl[p][3],
                      Bl + boff + p * (16 * APITCH));
            }
            #pragma unroll
            for (int mt = 0; mt < 4; ++mt)
                #pragma unroll
                for (int nt = 0; nt < 4; ++nt) {
                    const int p = nt >> 1, h = (nt & 1) * 2;
                    MMA16816(acc[mt][nt], ah[mt], bh[p][h], bh[p][h + 1]);
                    MMA16816(acc[mt][nt], ah[mt], bl[p][h], bl[p][h + 1]);
                    MMA16816(acc[mt][nt], al[mt], bh[p][h], bh[p][h + 1]);
                }
        }
        __syncthreads();
    }

    const int erow = lane >> 2, ecol = (lane & 3) * 2;
    #pragma unroll
    for (int mt = 0; mt < 4; ++mt) {
        #pragma unroll
        for (int nt = 0; nt < 4; ++nt) {
            int m0 = tm + wm + mt * 16 + erow;
            int n0 = tn + wn + nt * 8 + ecol;
            float bx = bias[n0], by = bias[n0 + 1];
            if (m0 < MTOT) {
                float2 o;
                o.x = (acc[mt][nt][0] + bx) * scale;
                o.y = (acc[mt][nt][1] + by) * scale;
                *(float2*)(Y + (size_t)m0 * D_ + n0) = o;
            }
            if (m0 + 8 < MTOT) {
                float2 o;
                o.x = (acc[mt][nt][2] + bx) * scale;
                o.y = (acc[mt][nt][3] + by) * scale;
                *(float2*)(Y + (size_t)(m0 + 8) * D_ + n0) = o;
            }
        }
    }
}

__global__ __launch_bounds__(256, 2) void mma_gemm_qkv(
    const __nv_bfloat16* __restrict__ Xhi, const __nv_bfloat16* __restrict__ Xlo,
    const __nv_bfloat16* __restrict__ Whi, const __nv_bfloat16* __restrict__ Wlo,
    const float* __restrict__ bq, const float* __restrict__ bk,
    const float* __restrict__ bv, float* __restrict__ Y)
{
    const int z = blockIdx.z;
    const size_t wo = (size_t)z * D_ * D_;
    const float* bias = (z == 0) ? bq : (z == 1) ? bk : bv;
    gemm_body(Xhi, Xlo, Whi + wo, Wlo + wo, bias,
              Y + (size_t)z * MTOT * D_, (z == 0) ? SCALE_Q : 1.f);
}

__global__ __launch_bounds__(256, 2) void mma_gemm(
    const __nv_bfloat16* __restrict__ Xhi, const __nv_bfloat16* __restrict__ Xlo,
    const __nv_bfloat16* __restrict__ Whi, const __nv_bfloat16* __restrict__ Wlo,
    const float* __restrict__ bias, float* __restrict__ Y, float scale)
{
    gemm_body(Xhi, Xlo, Whi, Wlo, bias, Y, scale);
}

// ============================================================================
// Fused flash attention (rows 0..255)
// ============================================================================
#define FPITCH 144
#define KVROWB (64 * FPITCH)
#define KVSTG  (4 * KVROWB)
#define FA_SMEM (2 * KVSTG)

__device__ __forceinline__ void load_kv(
    uint32_t st, int t0, size_t kvbase, int tid,
    const __nv_bfloat16* __restrict__ khi, const __nv_bfloat16* __restrict__ klo,
    const __nv_bfloat16* __restrict__ vhi, const __nv_bfloat16* __restrict__ vlo)
{
    #pragma unroll
    for (int j = 0; j < 8; ++j) {
        int g = tid + j * 256;
        int tens = g >> 9, i = g & 511, row = i >> 3, seg = i & 7;
        const __nv_bfloat16* bp = (tens == 0) ? khi : (tens == 1) ? klo
                                 : (tens == 2) ? vhi : vlo;
        const void* src = bp + kvbase + (size_t)(t0 + row) * D_ + seg * 8;
        uint32_t dst = st + tens * KVROWB + row * FPITCH + seg * 16;
        CP_ASYNC16(dst, src, (t0 + row) < S_ ? 16 : 0);
    }
}

__global__ __launch_bounds__(256, 1) void flash_attn(
    const __nv_bfloat16* __restrict__ qhi, const __nv_bfloat16* __restrict__ qlo,
    const __nv_bfloat16* __restrict__ khi, const __nv_bfloat16* __restrict__ klo,
    const __nv_bfloat16* __restrict__ vhi, const __nv_bfloat16* __restrict__ vlo,
    float* __restrict__ Xo)
{
    extern __shared__ char smem[];
    const uint32_t sb = smem_u32(smem);
    const int tid = threadIdx.x, wid = tid >> 5, lane = tid & 31;
    const int bh = blockIdx.x, b = bh >> 4, h = bh & 15;
    const int m0 = blockIdx.y * 128;
    const size_t kvbase = (size_t)b * S_ * D_ + h * HD_;

    #pragma unroll
    for (int j = 0; j < 8; ++j) {
        int g = tid + j * 256;
        int half = g >> 10, i = g & 1023, row = i >> 3, seg = i & 7;
        const __nv_bfloat16* src = (half ? qlo : qhi) + kvbase
                                 + (size_t)(m0 + row) * D_ + seg * 8;
        uint32_t dst = sb + half * KVSTG + row * FPITCH + seg * 16;
        CP_ASYNC16(dst, src, (m0 + row) < S_ ? 16 : 0);
    }
    CP_COMMIT(); CP_WAIT0();
    __syncthreads();

    uint32_t qh[4][4], ql[4][4];
    {
        const uint32_t base = sb + (uint32_t)(wid * 16 + (lane & 15)) * FPITCH
                            + (lane >> 4) * 16;
        #pragma unroll
        for (int kk = 0; kk < 4; ++kk) {
            LDSM4(qh[kk][0], qh[kk][1], qh[kk][2], qh[kk][3], base + kk * 32);
            LDSM4(ql[kk][0], ql[kk][1], ql[kk][2], ql[kk][3], base + KVSTG + kk * 32);
        }
    }
    __syncthreads();

    float acc_o[8][4] = {};
    float mrow[2] = {-1e30f, -1e30f}, lrow[2] = {0.f, 0.f};
    const int brow = ((lane >> 4) << 3) + (lane & 7);
    const int bk   = (lane >> 3) & 1;
    const int quad = lane & 3;

    load_kv(sb, 0, kvbase, tid, khi, klo, vhi, vlo);
    CP_COMMIT();

    #pragma unroll 1
    for (int kv = 0; kv < 5; ++kv) {
        CP_WAIT0();
        __syncthreads();
        const uint32_t Ks = sb + (kv & 1) * KVSTG;
        const uint32_t Vs = Ks + 2 * KVROWB;
        if (kv < 4) {
            load_kv(sb + ((kv + 1) & 1) * KVSTG, (kv + 1) * 64, kvbase, tid,
                    khi, klo, vhi, vlo);
            CP_COMMIT();
        }

        float s[8][4] = {};
        #pragma unroll
        for (int kk = 0; kk < 4; ++kk) {
            uint32_t kh[4][4], kl[4][4];
            #pragma unroll
            for (int p = 0; p < 4; ++p) {
                uint32_t ko = Ks + (uint32_t)(p * 16 + brow) * FPITCH + kk * 32 + bk * 16;
                LDSM4(kh[p][0], kh[p][1], kh[p][2], kh[p][3], ko);
                LDSM4(kl[p][0], kl[p][1], kl[p][2], kl[p][3], ko + KVROWB);
            }
            #pragma unroll
            for (int p = 0; p < 4; ++p) {
                MMA16816(s[2*p],   qh[kk], kh[p][0], kh[p][1]);
                MMA16816(s[2*p+1], qh[kk], kh[p][2], kh[p][3]);
                MMA16816(s[2*p],   qh[kk], kl[p][0], kl[p][1]);
                MMA16816(s[2*p+1], qh[kk], kl[p][2], kl[p][3]);
                MMA16816(s[2*p],   ql[kk], kh[p][0], kh[p][1]);
                MMA16816(s[2*p+1], ql[kk], kh[p][2], kh[p][3]);
            }
        }

        if (kv == 4) {
            #pragma unroll
            for (int nt = 0; nt < 8; ++nt)
                #pragma unroll
                for (int rg = 0; rg < 4; ++rg) {
                    int col = 256 + nt * 8 + quad * 2 + (rg & 1);
                    if (col >= S_) s[nt][rg] = -1e30f;
                }
        }

        #pragma unroll
        for (int rr = 0; rr < 2; ++rr) {
            float mx = -1e30f;
            #pragma unroll
            for (int nt = 0; nt < 8; ++nt)
                mx = fmaxf(mx, fmaxf(s[nt][2*rr], s[nt][2*rr+1]));
            mx = fmaxf(mx, __shfl_xor_sync(0xffffffffu, mx, 1));
            mx = fmaxf(mx, __shfl_xor_sync(0xffffffffu, mx, 2));
            float mnew = fmaxf(mrow[rr], mx);
            float alpha = fexp(mrow[rr] - mnew);
            mrow[rr] = mnew;
            float sum = 0.f;
            #pragma unroll
            for (int nt = 0; nt < 8; ++nt) {
                float p0 = fexp(s[nt][2*rr]   - mnew);
                float p1 = fexp(s[nt][2*rr+1] - mnew);
                s[nt][2*rr] = p0; s[nt][2*rr+1] = p1;
                sum += p0 + p1;
            }
            sum += __shfl_xor_sync(0xffffffffu, sum, 1);
            sum += __shfl_xor_sync(0xffffffffu, sum, 2);
            lrow[rr] = lrow[rr] * alpha + sum;
            #pragma unroll
            for (int nt = 0; nt < 8; ++nt) {
                acc_o[nt][2*rr]   *= alpha;
                acc_o[nt][2*rr+1] *= alpha;
            }
        }

        #pragma unroll
        for (int kk = 0; kk < 4; ++kk) {
            uint32_t ph[4], pl[4];
            #pragma unroll
            for (int rg = 0; rg < 4; ++rg) {
                int nt = 2 * kk + (rg >> 1);
                float p0 = s[nt][(rg & 1) * 2];
                float p1 = s[nt][(rg & 1) * 2 + 1];
                __nv_bfloat162 hb = __floats2bfloat162_rn(p0, p1);
                float l0 = p0 - __bfloat162float(hb.x);
                float l1 = p1 - __bfloat162float(hb.y);
                __nv_bfloat162 lb = __floats2bfloat162_rn(l0, l1);
                ph[rg] = *(uint32_t*)&hb;
                pl[rg] = *(uint32_t*)&lb;
            }
            uint32_t vh[4][4], vl[4][4];
            #pragma unroll
            for (int p = 0; p < 4; ++p) {
                uint32_t vo = Vs + (uint32_t)(kk * 16 + (lane & 15)) * FPITCH
                            + p * 32 + (lane >> 4) * 16;
                LDSM4T(vh[p][0], vh[p][1], vh[p][2], vh[p][3], vo);
                LDSM4T(vl[p][0], vl[p][1], vl[p][2], vl[p][3], vo + KVROWB);
            }
            #pragma unroll
            for (int p = 0; p < 4; ++p) {
                MMA16816(acc_o[2*p],   ph, vh[p][0], vh[p][1]);
                MMA16816(acc_o[2*p+1], ph, vh[p][2], vh[p][3]);
                MMA16816(acc_o[2*p],   ph, vl[p][0], vl[p][1]);
                MMA16816(acc_o[2*p+1], ph, vl[p][2], vl[p][3]);
                MMA16816(acc_o[2*p],   pl, vh[p][0], vh[p][1]);
                MMA16816(acc_o[2*p+1], pl, vh[p][2], vh[p][3]);
            }
        }
    }

    {
        const int r = lane >> 2, q2 = quad * 2;
        #pragma unroll
        for (int rr = 0; rr < 2; ++rr) {
            int m = m0 + wid * 16 + r + rr * 8;
            if (m < S_) {
                float inv = 1.f / lrow[rr];
                float* op = Xo + ((size_t)b * S_ + m) * D_ + h * HD_ + q2;
                #pragma unroll
                for (int nt = 0; nt < 8; ++nt) {
                    float2 o;
                    o.x = acc_o[nt][2*rr]   * inv;
                    o.y = acc_o[nt][2*rr+1] * inv;
                    *(float2*)(op + nt * 8) = o;
                }
            }
        }
    }
}

// ============================================================================
// attn_tail: query row s = 256
// ============================================================================
#define TAIL_SMEM ((257 * 65 + 64 + 257 + 256) * 4)
__global__ __launch_bounds__(256) void attn_tail(
    const __nv_bfloat16* __restrict__ qhi, const __nv_bfloat16* __restrict__ qlo,
    const __nv_bfloat16* __restrict__ khi, const __nv_bfloat16* __restrict__ klo,
    const __nv_bfloat16* __restrict__ vhi, const __nv_bfloat16* __restrict__ vlo,
    float* __restrict__ Xo)
{
    extern __shared__ float fs[];
    float* ks  = fs;
    float* q   = ks + 257 * 65;
    float* p   = q + 64;
    float* red = p + 257;
    const int t = threadIdx.x;
    const int bh = blockIdx.x, b = bh >> 4, h = bh & 15;
    const size_t base = (size_t)b * S_ * D_ + h * HD_;

    if (t < 64) {
        size_t o = base + (size_t)256 * D_ + t;
        q[t] = __bfloat162float(qhi[o]) + __bfloat162float(qlo[o]);
    }
    for (int i = t; i < 257 * 64; i += 256) {
        int row = i >> 6, d = i & 63;
        size_t o = base + (size_t)row * D_ + d;
        ks[row * 65 + d] = __bfloat162float(khi[o]) + __bfloat162float(klo[o]);
    }
    __syncthreads();

    float v0 = 0.f, v1 = -1e30f;
    {
        const float* kr = ks + t * 65;
        #pragma unroll 8
        for (int d = 0; d < 64; ++d) v0 = fmaf(q[d], kr[d], v0);
    }
    if (t == 0) {
        v1 = 0.f;
        const float* kr = ks + 256 * 65;
        #pragma unroll 8
        for (int d = 0; d < 64; ++d) v1 = fmaf(q[d], kr[d], v1);
    }

    red[t] = fmaxf(v0, v1);
    __syncthreads();
    #pragma unroll
    for (int o = 128; o; o >>= 1) {
        if (t < o) red[t] = fmaxf(red[t], red[t + o]);
        __syncthreads();
    }
    float rmax = red[0];
    __syncthreads();
    float e0 = fexp(v0 - rmax);
    float e1 = (t == 0) ? fexp(v1 - rmax) : 0.f;
    red[t] = e0 + e1;
    __syncthreads();
    #pragma unroll
    for (int o = 128; o; o >>= 1) {
        if (t < o) red[t] += red[t + o];
        __syncthreads();
    }
    float inv = 1.f / red[0];
    p[t] = e0 * inv;
    if (t == 0) p[256] = e1 * inv;
    __syncthreads();

    if (t < 64) {
        float o = 0.f;
        for (int tt = 0; tt < S_; ++tt) {
            size_t off = base + (size_t)tt * D_ + t;
            o = fmaf(p[tt], __bfloat162float(vhi[off]) + __bfloat162float(vlo[off]), o);
        }
        Xo[((size_t)b * S_ + 256) * D_ + h * HD_ + t] = o;
    }
}

// ============================================================================
// xa: grid (B, KE, 16*nproj); z/16 selects projection (A matrix + dst slice)
// ============================================================================
__global__ __launch_bounds__(256) void xa_kernel(
    const float* __restrict__ X,
    const float* __restrict__ A0, const float* __restrict__ A1,
    const float* __restrict__ A2,
    const int* __restrict__ idx, float* __restrict__ xa)
{
    int b = blockIdx.x, slot = blockIdx.y;
    int proj = blockIdx.z >> 4, zz = blockIdx.z & 15;
    int rh = zz >> 3, sc = zz & 7;
    const float* A = (proj == 0) ? A0 : (proj == 1) ? A1 : A2;
    float* xad = xa + (size_t)proj * B_ * KE_ * S_ * R_;
    int sbase = sc * 33;
    int smax = min(S_, sbase + 33);
    int e = idx[b * KE_ + slot];
    __shared__ float As[8][D_];
    const float* Ap = A + ((size_t)e * R_ + rh * 8) * D_;
    for (int i = threadIdx.x; i < 8 * D_ / 4; i += 256)
        ((float4*)As)[i] = ((const float4*)Ap)[i];
    __syncthreads();

    int w = threadIdx.x >> 5, lane = threadIdx.x & 31;
    for (int s4 = sbase + w * 4; s4 < smax; s4 += 32) {
        float sum[8][4];
        #pragma unroll
        for (int r = 0; r < 8; r++)
            #pragma unroll
            for (int si = 0; si < 4; si++) sum[r][si] = 0.f;

        #pragma unroll 1
        for (int c = 0; c < 8; c++) {
            float4 xv[4];
            #pragma unroll
            for (int si = 0; si < 4; si++) {
                int s = s4 + si;
                xv[si] = (s < S_)
                    ? *(const float4*)(X + ((size_t)b * S_ + s) * D_ + c * 128 + lane * 4)
                    : make_float4(0.f, 0.f, 0.f, 0.f);
            }
            #pragma unroll
            for (int r = 0; r < 8; r++) {
                float4 av = *(const float4*)&As[r][c * 128 + lane * 4];
                #pragma unroll
                for (int si = 0; si < 4; si++)
                    sum[r][si] = fmaf(xv[si].x, av.x,
                                 fmaf(xv[si].y, av.y,
                                 fmaf(xv[si].z, av.z,
                                 fmaf(xv[si].w, av.w, sum[r][si]))));
            }
        }
        #pragma unroll
        for (int r = 0; r < 8; r++)
            #pragma unroll
            for (int si = 0; si < 4; si++) {
                float v = sum[r][si];
                #pragma unroll
                for (int o = 16; o; o >>= 1) v += __shfl_xor_sync(0xffffffffu, v, o);
                int s = s4 + si;
                if (lane == 0 && s < S_)
                    xad[(((size_t)b * KE_ + slot) * S_ + s) * R_ + rh * 8 + r] = v;
            }
    }
}

// ============================================================================
// lora_add: Y += gated LoRA (fp32, O projection)
// ============================================================================
__global__ __launch_bounds__(256) void lora_add(
    const float* __restrict__ Bm, const int* __restrict__ idx,
    const float* __restrict__ gates, const float* __restrict__ xa,
    float* __restrict__ Y, float scale)
{
    int b = blockIdx.x;
    int cn = blockIdx.y << 6;
    int t = threadIdx.x;
    __shared__ float Bs[2][64][17];
    __shared__ float xs[2][64][17];
    int e0 = idx[b * KE_], e1 = idx[b * KE_ + 1];
    float g0 = gates[b * KE_] * scale, g1 = gates[b * KE_ + 1] * scale;

    for (int i = t; i < 2048; i += 256) {
        int slot = i >> 10, rem = i & 1023, c = rem >> 4, r = rem & 15;
        Bs[slot][c][r] = Bm[((size_t)(slot ? e1 : e0) * D_ + cn + c) * R_ + r];
    }

    int c = t & 63, sq = t >> 6;
    for (int s0 = 0; s0 < S_; s0 += 64) {
        __syncthreads();
        for (int i = t; i < 2048; i += 256) {
            int slot = i >> 10, rem = i & 1023, si = rem >> 4, r = rem & 15;
            int s = s0 + si;
            float v = (s < S_) ? xa[(((size_t)b * KE_ + slot) * S_ + s) * R_ + r] : 0.f;
            xs[slot][si][r] = v * (slot ? g1 : g0);
        }
        __syncthreads();
        for (int si = sq; si < 64; si += 4) {
            int s = s0 + si;
            if (s >= S_) break;
            float sum = 0.f;
            #pragma unroll
            for (int r = 0; r < 16; r++) {
                sum = fmaf(xs[0][si][r], Bs[0][c][r], sum);
                sum = fmaf(xs[1][si][r], Bs[1][c][r], sum);
            }
            Y[((size_t)b * S_ + s) * D_ + cn + c] += sum;
        }
    }
}

// ============================================================================
// lora_split3: out = Yin + gated LoRA, bf16 hi/lo; grid.z selects q/k/v
// ============================================================================
__global__ __launch_bounds__(256) void lora_split3(
    const float* __restrict__ Bq, const float* __restrict__ Bk,
    const float* __restrict__ Bv,
    const int* __restrict__ idx, const float* __restrict__ gates,
    const float* __restrict__ xa, const float* __restrict__ Yin,
    __nv_bfloat16* __restrict__ qhi, __nv_bfloat16* __restrict__ qlo,
    __nv_bfloat16* __restrict__ khi, __nv_bfloat16* __restrict__ klo,
    __nv_bfloat16* __restrict__ vhi, __nv_bfloat16* __restrict__ vlo)
{
    const int z = blockIdx.z;
    const float* Bm = (z == 0) ? Bq : (z == 1) ? Bk : Bv;
    const float* Yz = Yin + (size_t)z * MTOT * D_;
    const float* xaz = xa + (size_t)z * B_ * KE_ * S_ * R_;
    __nv_bfloat16* Yhi = (z == 0) ? qhi : (z == 1) ? khi : vhi;
    __nv_bfloat16* Ylo = (z == 0) ? qlo : (z == 1) ? klo : vlo;
    const float scale = (z == 0) ? SCALE_Q : 1.f;

    int b = blockIdx.x;
    int cn = blockIdx.y << 6;
    int t = threadIdx.x;
    __shared__ float Bs[2][64][17];
    __shared__ float xs[2][64][17];
    int e0 = idx[b * KE_], e1 = idx[b * KE_ + 1];
    float g0 = gates[b * KE_] * scale, g1 = gates[b * KE_ + 1] * scale;

    for (int i = t; i < 2048; i += 256) {
        int slot = i >> 10, rem = i & 1023, c = rem >> 4, r = rem & 15;
        Bs[slot][c][r] = Bm[((size_t)(slot ? e1 : e0) * D_ + cn + c) * R_ + r];
    }

    int c = t & 63, sq = t >> 6;
    for (int s0 = 0; s0 < S_; s0 += 64) {
        __syncthreads();
        for (int i = t; i < 2048; i += 256) {
            int slot = i >> 10, rem = i & 1023, si = rem >> 4, r = rem & 15;
            int s = s0 + si;
            float v = (s < S_) ? xaz[(((size_t)b * KE_ + slot) * S_ + s) * R_ + r] : 0.f;
            xs[slot][si][r] = v * (slot ? g1 : g0);
        }
        __syncthreads();
        for (int si = sq; si < 64; si += 4) {
            int s = s0 + si;
            if (s >= S_) break;
            float sum = 0.f;
            #pragma unroll
            for (int r = 0; r < 16; r++) {
                sum = fmaf(xs[0][si][r], Bs[0][c][r], sum);
                sum = fmaf(xs[1][si][r], Bs[1][c][r], sum);
            }
            size_t off = ((size_t)b * S_ + s) * D_ + cn + c;
            float v = Yz[off] + sum;
            __nv_bfloat16 hb = __float2bfloat16(v);
            Yhi[off] = hb;
            Ylo[off] = __float2bfloat16(v - __bfloat162float(hb));
        }
    }
}

// ---------------- host launcher --------------------------------------------
extern "C" void kernel_launch(void* const* d_in, const int* in_sizes, int n_in,
                              void* d_out, int out_size)
{
    const float* hs    = (const float*)d_in[0];
    const int*   idx   = (const int*)  d_in[1];
    const float* gates = (const float*)d_in[2];
    const float* wq = (const float*)d_in[3];  const float* Aq = (const float*)d_in[4];
    const float* Bq = (const float*)d_in[5];  const float* bq = (const float*)d_in[6];
    const float* wk = (const float*)d_in[7];  const float* Ak = (const float*)d_in[8];
    const float* Bk = (const float*)d_in[9];  const float* bk = (const float*)d_in[10];
    const float* wv = (const float*)d_in[11]; const float* Av = (const float*)d_in[12];
    const float* Bv = (const float*)d_in[13]; const float* bv = (const float*)d_in[14];
    const float* wo = (const float*)d_in[15]; const float* Ao = (const float*)d_in[16];
    const float* Bo = (const float*)d_in[17]; const float* bo = (const float*)d_in[18];
    float* out = (float*)d_out;

    float *tmp, *x2, *xa;
    __nv_bfloat16 *xhi, *xlo, *whi, *wlo, *qhi, *qlo, *khi, *klo, *vhi, *vlo;
    cudaGetSymbolAddress((void**)&tmp, g_tmp);
    cudaGetSymbolAddress((void**)&x2,  g_x2);
    cudaGetSymbolAddress((void**)&xa,  g_xa);
    cudaGetSymbolAddress((void**)&xhi, g_xhi);
    cudaGetSymbolAddress((void**)&xlo, g_xlo);
    cudaGetSymbolAddress((void**)&whi, g_whi);
    cudaGetSymbolAddress((void**)&wlo, g_wlo);
    cudaGetSymbolAddress((void**)&qhi, g_qhi);
    cudaGetSymbolAddress((void**)&qlo, g_qlo);
    cudaGetSymbolAddress((void**)&khi, g_khi);
    cudaGetSymbolAddress((void**)&klo, g_klo);
    cudaGetSymbolAddress((void**)&vhi, g_vhi);
    cudaGetSymbolAddress((void**)&vlo, g_vlo);

    cudaFuncSetAttribute(mma_gemm_qkv, cudaFuncAttributeMaxDynamicSharedMemorySize, GEMM_SMEM);
    cudaFuncSetAttribute(mma_gemm, cudaFuncAttributeMaxDynamicSharedMemorySize, GEMM_SMEM);
    cudaFuncSetAttribute(flash_attn, cudaFuncAttributeMaxDynamicSharedMemorySize, FA_SMEM);
    cudaFuncSetAttribute(attn_tail, cudaFuncAttributeMaxDynamicSharedMemorySize, TAIL_SMEM);

    const int nx4 = MTOT * D_ / 4;
    const int nw4 = D_ * D_ / 4;

    // inputs -> bf16 splits
    split_bf16<<<(nx4 + 255) / 256, 256>>>((const float4*)hs, (uint2*)xhi, (uint2*)xlo, nx4);
    split_w3<<<dim3((nw4 + 255) / 256, 3), 256>>>(
        (const float4*)wq, (const float4*)wk, (const float4*)wv, (uint2*)whi, (uint2*)wlo);

    // xa for q/k/v in one launch
    xa_kernel<<<dim3(B_, KE_, 48), 256>>>(hs, Aq, Ak, Av, idx, xa);

    // fused QKV GEMM
    mma_gemm_qkv<<<dim3(D_ / 128, (MTOT + 127) / 128, 3), 256, GEMM_SMEM>>>(
        xhi, xlo, whi, wlo, bq, bk, bv, tmp);

    // LoRA + bf16 split for q/k/v in one launch
    lora_split3<<<dim3(B_, D_ / 64, 3), 256>>>(
        Bq, Bk, Bv, idx, gates, xa, tmp, qhi, qlo, khi, klo, vhi, vlo);

    // attention
    flash_attn<<<dim3(B_ * H_, 2), 256, FA_SMEM>>>(qhi, qlo, khi, klo, vhi, vlo, x2);
    attn_tail<<<B_ * H_, 256, TAIL_SMEM>>>(qhi, qlo, khi, klo, vhi, vlo, x2);

    // O projection
    xa_kernel<<<dim3(B_, KE_, 16), 256>>>(x2, Ao, Ao, Ao, idx, xa);
    split_bf16<<<(nx4 + 255) / 256, 256>>>((const float4*)x2, (uint2*)xhi, (uint2*)xlo, nx4);
    split_bf16<<<(nw4 + 255) / 256, 256>>>((const float4*)wo, (uint2*)whi, (uint2*)wlo, nw4);
    mma_gemm<<<dim3(D_ / 128, (MTOT + 127) / 128), 256, GEMM_SMEM>>>(
        xhi, xlo, whi, wlo, bo, out, 1.f);
    lora_add<<<dim3(B_, D_ / 64), 256>>>(Bo, idx, gates, xa, out, 1.f);
}